// round 13
// baseline (speedup 1.0000x reference)
#include <cuda_runtime.h>
#include <cuda_fp16.h>
#include <cstdint>

#define NCLS 80
#define NCH  81
#define TK   100
#define BN   8
#define CN   256
#define HN   128
#define WN   128
#define HW   (HN*WN)
#define PP   130
#define NPX  (PP*PP)

// ---------------- scratch (device globals) ---------------------------------
__device__ __half g_xh[(size_t)BN*NPX*CN];   // NHWC padded, fp16-hi
__device__ __half g_xl[(size_t)BN*NPX*CN];   // NHWC padded, fp16-lo
// B in mma-fragment order: [k16 index][ogp(16)][lane(32)] -> uint4
__device__ uint4  g_wfh[73728];              // 144*16*32 uint4
__device__ uint4  g_wfl[73728];
__device__ float  g_y[(size_t)BN*HW*CN];     // relu(conv3x3), NHWC
__device__ float  g_w2t[CN*NCH];
__device__ float  g_pstar[BN*HW];
__device__ int    g_cls[BN*HW];
__device__ float  g_scores[BN*HW];
__device__ int    g_topidx[BN*TK];

// ---------------- PTX helpers ----------------------------------------------
__device__ __forceinline__ uint32_t smem_u32(const void* p){
    uint32_t a;
    asm("{ .reg .u64 t; cvta.to.shared.u64 t, %1; cvt.u32.u64 %0, t; }" : "=r"(a) : "l"(p));
    return a;
}
__device__ __forceinline__ void cpa16(uint32_t dst, const void* src){
    asm volatile("cp.async.cg.shared.global [%0], [%1], 16;" :: "r"(dst), "l"(src));
}
#define CP_COMMIT() asm volatile("cp.async.commit_group;" ::: "memory")
#define CP_WAIT1()  asm volatile("cp.async.wait_group 1;" ::: "memory")
#define CP_WAIT0()  asm volatile("cp.async.wait_group 0;" ::: "memory")

__device__ __forceinline__ void mma16816(float* d, const uint32_t* a, const uint32_t* b){
    asm volatile("mma.sync.aligned.m16n8k16.row.col.f32.f16.f16.f32 "
        "{%0,%1,%2,%3}, {%4,%5,%6,%7}, {%8,%9}, {%0,%1,%2,%3};"
        : "+f"(d[0]), "+f"(d[1]), "+f"(d[2]), "+f"(d[3])
        : "r"(a[0]), "r"(a[1]), "r"(a[2]), "r"(a[3]), "r"(b[0]), "r"(b[1]));
}
// fp16-accumulate variant (corrections)
__device__ __forceinline__ void mma16816h(uint32_t* d, const uint32_t* a, const uint32_t* b){
    asm volatile("mma.sync.aligned.m16n8k16.row.col.f16.f16.f16.f16 "
        "{%0,%1}, {%2,%3,%4,%5}, {%6,%7}, {%0,%1};"
        : "+r"(d[0]), "+r"(d[1])
        : "r"(a[0]), "r"(a[1]), "r"(a[2]), "r"(a[3]), "r"(b[0]), "r"(b[1]));
}
__device__ __forceinline__ void ldm4(uint32_t* r, uint32_t addr){
    asm volatile("ldmatrix.sync.aligned.m8n8.x4.shared.b16 {%0,%1,%2,%3}, [%4];"
        : "=r"(r[0]), "=r"(r[1]), "=r"(r[2]), "=r"(r[3]) : "r"(addr));
}

// ---------------- T0: NCHW -> padded NHWC fp16 hi/lo ------------------------
__global__ __launch_bounds__(256) void t_half(const float* __restrict__ x){
    __shared__ float s[256][33];
    const int b = blockIdx.y;
    const int px0 = blockIdx.x*32;
    const int tid = threadIdx.x;
    const int pxl = tid & 31, cg = tid >> 5;
    const int p = px0 + pxl;
    const int ph = p / PP, pw = p % PP;
    const bool in = (p < NPX) && ph >= 1 && ph <= 128 && pw >= 1 && pw <= 128;
    const float* xp = x + (size_t)b*CN*HW + (size_t)(ph-1)*WN + (pw-1);
    #pragma unroll 8
    for (int i=0;i<32;i++){
        int c = i*8 + cg;
        s[c][pxl] = in ? xp[(size_t)c*HW] : 0.f;
    }
    __syncthreads();
    for (int j=0;j<32;j++){
        int px = px0 + j;
        if (px >= NPX) break;
        float v  = s[tid][j];
        __half hi = __float2half_rn(v);
        __half lo = __float2half_rn(v - __half2float(hi));
        size_t o = ((size_t)b*NPX + px)*CN + tid;
        g_xh[o] = hi;
        g_xl[o] = lo;
    }
}

// ---------------- K0: weight prep (fragment order) + w2t --------------------
__global__ void k0_wprep(const float* __restrict__ w1,
                         const float* __restrict__ w2){
    int t = blockIdx.x*256 + threadIdx.x;
    if (t < 144*16*32*4){
        int j    = t & 3;
        int l    = (t>>2) & 31;
        int ogp  = (t>>7) & 15;
        int k16  = t >> 11;
        int tap  = k16 >> 4;
        int oc = (ogp*2 + (j>>1))*8 + (l>>2);
        int k  = (k16 & 15)*16 + (j&1)*8 + (l&3)*2;
        float v0 = w1[((size_t)oc*CN + k  )*9 + tap];
        float v1 = w1[((size_t)oc*CN + k+1)*9 + tap];
        __half h0 = __float2half_rn(v0);
        __half h1 = __float2half_rn(v1);
        __half l0 = __float2half_rn(v0 - __half2float(h0));
        __half l1 = __float2half_rn(v1 - __half2float(h1));
        ((uint32_t*)g_wfh)[t] = (uint32_t)__half_as_ushort(h0) |
                                ((uint32_t)__half_as_ushort(h1) << 16);
        ((uint32_t*)g_wfl)[t] = (uint32_t)__half_as_ushort(l0) |
                                ((uint32_t)__half_as_ushort(l1) << 16);
    }
    if (t < CN*NCH){
        int cin = t/NCH, oc = t%NCH;
        g_w2t[t] = w2[oc*CN + cin];
    }
}

// ---------------- K1: conv3x3 via mma.sync fp16 split ------------------------
// grid (128 h, 4 octile, 8 b); 256 threads = 8 warps (2M x 4N), warp m64n16.
// Main pass hi*whi in fp32 acc; corrections hi*wlo + lo*whi in fp16 acc.
// A: 3-stage cp.async ring, 64 cin/stage (128B rows), swizzle chunk^=(row&7).
// B: direct LDG.128 from fragment-ordered g_wfh/g_wfl. 2 CTAs/SM.
#define STG_SZ 32768u
#define AL_OFF 16384u

__global__ __launch_bounds__(256,2) void kmma(const float* __restrict__ b1){
    extern __shared__ __align__(16) char smem[];
    const uint32_t sb = smem_u32(smem);
    const int tid  = threadIdx.x;
    const int lane = tid & 31, wid = tid >> 5;
    const int wm = wid >> 2, wn = wid & 3;
    const int h  = blockIdx.x;
    const int ocb = blockIdx.y * 64;
    const int bb = blockIdx.z;

    // A fill: row = tid>>1 (0..127, 128B rows), half=(tid&1) -> chunks 4h..4h+3
    const int lrow = tid >> 1, lhalf = tid & 1;
    const uint32_t fsw = (uint32_t)(lrow & 7);
    const int fc0 = 4*lhalf;

    auto load_stage = [&](int g, int buf){
        const int tap = g >> 2, kc = g & 3;            // kc: 64-channel chunk
        const int ky = tap/3, kx = tap%3;
        const uint32_t sbase = sb + buf*STG_SZ;
        const size_t apix = (size_t)bb*NPX + (size_t)(h + ky)*PP + kx + lrow;
        const size_t aoff = apix*CN + kc*64 + fc0*8;
        #pragma unroll
        for (int i=0;i<4;i++){
            const uint32_t dst = (uint32_t)lrow*128u + (((uint32_t)(fc0+i)) ^ fsw)*16u;
            cpa16(sbase          + dst, g_xh + aoff + i*8);
            cpa16(sbase + AL_OFF + dst, g_xl + aoff + i*8);
        }
        CP_COMMIT();
    };

    float    acc [4][2][4];     // hi*whi, fp32
    uint32_t accc[4][2][2];     // corrections, fp16x2
    #pragma unroll
    for (int mt=0;mt<4;mt++)
        #pragma unroll
        for (int nt=0;nt<2;nt++){
            #pragma unroll
            for (int q=0;q<4;q++) acc[mt][nt][q] = 0.f;
            accc[mt][nt][0] = 0u; accc[mt][nt][1] = 0u;
        }

    load_stage(0, 0);
    load_stage(1, 1);

    // A fragment addressing: row = wm*64+mt*16+(lane&15); swizzle key = lane&7
    const uint32_t rA  = (uint32_t)(lane & 15);
    const uint32_t sA  = (uint32_t)(lane & 7);
    const uint32_t cA0 = (uint32_t)(lane >> 4);
    const int ogp = blockIdx.y*4 + wn;   // one ogp (16 oc) per warp

    for (int g=0; g<36; g++){
        const int buf = g % 3;
        CP_WAIT1();
        __syncthreads();
        if (g + 2 < 36) load_stage(g+2, (g+2)%3);

        const uint32_t sbase  = sb + buf*STG_SZ;
        const uint32_t aBaseH = sbase          + (uint32_t)(wm*64 + (int)rA)*128u;
        const uint32_t aBaseL = sbase + AL_OFF + (uint32_t)(wm*64 + (int)rA)*128u;

        #pragma unroll
        for (int q=0; q<4; q++){
            // B fragments: one ogp per warp -> single uint4 each
            const int fb = ((g*4 + q)*16 + ogp)*32 + lane;
            const uint4 bq = __ldg(&g_wfh[fb]);
            const uint4 cq = __ldg(&g_wfl[fb]);
            uint32_t bh[2][2] = {{bq.x,bq.y},{bq.z,bq.w}};
            uint32_t bl[2][2] = {{cq.x,cq.y},{cq.z,cq.w}};

            const uint32_t gA = ((uint32_t)(q*2) + cA0) ^ sA;
            #pragma unroll
            for (int mt=0;mt<4;mt++){
                uint32_t af[4];
                ldm4(af, aBaseH + (uint32_t)(mt*16)*128u + gA*16u);
                #pragma unroll
                for (int nt=0;nt<2;nt++){
                    mma16816 (acc [mt][nt], af, bh[nt]);
                    mma16816h(accc[mt][nt], af, bl[nt]);
                }
                ldm4(af, aBaseL + (uint32_t)(mt*16)*128u + gA*16u);
                #pragma unroll
                for (int nt=0;nt<2;nt++)
                    mma16816h(accc[mt][nt], af, bh[nt]);
            }
        }
    }
    CP_WAIT0();

    // epilogue: fp32 main + fp16 corrections + bias + relu -> y NHWC
    #pragma unroll
    for (int nt=0;nt<2;nt++){
        const int cc = ocb + wn*16 + nt*8 + (lane & 3)*2;
        const float bz0 = b1[cc], bz1 = b1[cc+1];
        #pragma unroll
        for (int mt=0;mt<4;mt++){
            const int w = wm*64 + mt*16 + (lane >> 2);
            const size_t pix = (size_t)bb*HW + (size_t)h*WN + w;
            float2 cA2 = __half22float2(*(__half2*)&accc[mt][nt][0]);
            float2 cB2 = __half22float2(*(__half2*)&accc[mt][nt][1]);
            float2 v0, v1;
            v0.x = fmaxf(acc[mt][nt][0] + cA2.x + bz0, 0.f);
            v0.y = fmaxf(acc[mt][nt][1] + cA2.y + bz1, 0.f);
            v1.x = fmaxf(acc[mt][nt][2] + cB2.x + bz0, 0.f);
            v1.y = fmaxf(acc[mt][nt][3] + cB2.y + bz1, 0.f);
            *(float2*)&g_y[pix*CN + cc]     = v0;
            *(float2*)&g_y[(pix+8)*CN + cc] = v1;
        }
    }
}

// ---------------- K2: conv1x1 + bias + softmax stats + logits out ----------
__global__ __launch_bounds__(256,2) void k2_conv1(const float* __restrict__ b2,
                                                  float* __restrict__ out){
    __shared__ __align__(16) float ws2[32][84];
    const int tid = threadIdx.x;
    const int gp  = blockIdx.x*256 + tid;
    const int b   = gp >> 14, hw = gp & (HW-1);

    float acc[NCH];
    #pragma unroll
    for (int o=0;o<NCH;o++) acc[o] = 0.f;

    const float* yb = g_y + (size_t)gp*CN;      // NHWC: contiguous 256 per pixel
    for (int cc=0; cc<CN; cc+=32){
        __syncthreads();
        #pragma unroll
        for (int i=tid; i<32*NCH; i+=256)
            ws2[i/NCH][i%NCH] = g_w2t[(cc + i/NCH)*NCH + (i%NCH)];
        __syncthreads();
        #pragma unroll
        for (int j=0;j<8;j++){
            const float4 v4 = *(const float4*)(yb + cc + j*4);
            const float vv[4] = {v4.x, v4.y, v4.z, v4.w};
            #pragma unroll
            for (int u=0;u<4;u++){
                const int cl = j*4 + u;
                const float v = vv[u];
                #pragma unroll
                for (int o4=0;o4<20;o4++){
                    float4 w4 = *(const float4*)&ws2[cl][o4*4];
                    acc[o4*4+0] += v*w4.x; acc[o4*4+1] += v*w4.y;
                    acc[o4*4+2] += v*w4.z; acc[o4*4+3] += v*w4.w;
                }
                acc[80] += v*ws2[cl][80];
            }
        }
    }
    #pragma unroll
    for (int o=0;o<NCH;o++) acc[o] += b2[o];

    float m = acc[0];
    #pragma unroll
    for (int o=1;o<NCH;o++) m = fmaxf(m, acc[o]);
    float s = 0.f;
    #pragma unroll
    for (int o=0;o<NCH;o++) s += __expf(acc[o]-m);
    int cls = 0; float best = acc[0];
    #pragma unroll
    for (int o=1;o<NCLS;o++) if (acc[o] > best){ best = acc[o]; cls = o; }

    g_pstar[gp] = __expf(best - m)/s;
    g_cls[gp]   = cls;

    float* lo = out + 409600 + (size_t)b*NCH*HW + hw;
    #pragma unroll
    for (int o=0;o<NCH;o++) lo[(size_t)o*HW] = acc[o];
}

// ---------------- K3: local-max boost + score map --------------------------
__global__ void k3_boost(){
    const int gp = blockIdx.x*256 + threadIdx.x;
    const int b = gp>>14, hw = gp&(HW-1);
    const int h = hw>>7,  w  = hw&127;
    const float p = g_pstar[gp];
    const int   c = g_cls[gp];
    bool ok = (p >= 1e-6f);
    #pragma unroll
    for (int dy=-1; dy<=1; dy++)
        #pragma unroll
        for (int dx=-1; dx<=1; dx++){
            if (dy==0 && dx==0) continue;
            int nh = h+dy, nw = w+dx;
            if (nh<0 || nh>=HN || nw<0 || nw>=WN) continue;
            int n = (b<<14) + nh*WN + nw;
            if (g_cls[n]==c && p < g_pstar[n]) ok = false;
        }
    g_scores[gp] = p + (ok ? 1.f : 0.f);
}

// ---------------- K4: per-batch top-100 via bitonic sort -------------------
__global__ void k4_topk(){
    extern __shared__ unsigned long long sk[];
    const int N = HW;
    const int b = blockIdx.x, tid = threadIdx.x;
    for (int i=tid; i<N; i+=1024){
        unsigned sb2 = __float_as_uint(g_scores[(b<<14)+i]);
        sk[i] = ((unsigned long long)sb2<<32) | (unsigned)(0xFFFFFFFFu - (unsigned)i);
    }
    __syncthreads();
    for (int k=2; k<=N; k<<=1){
        for (int j=k>>1; j>0; j>>=1){
            for (int i=tid; i<N; i+=1024){
                int ixj = i^j;
                if (ixj > i){
                    unsigned long long a = sk[i], c = sk[ixj];
                    bool up = (i&k)==0;
                    if (up ? (a<c) : (a>c)){ sk[i]=c; sk[ixj]=a; }
                }
            }
            __syncthreads();
        }
    }
    if (tid < TK){
        unsigned low = (unsigned)sk[tid];
        g_topidx[b*TK + tid] = (int)(0xFFFFFFFFu - low);
    }
}

// ---------------- K5: gather proposals + pos embeddings --------------------
__global__ void k5_gather(const float* __restrict__ x,
                          const float* __restrict__ pe,
                          float* __restrict__ out){
    const int t = blockIdx.x*256 + threadIdx.x;
    if (t >= BN*CN*TK) return;
    const int k = t % TK;
    const int c = (t / TK) % CN;
    const int b = t / (TK*CN);
    const int idx = g_topidx[b*TK + k];
    out[t]            = x [(size_t)(b*CN + c)*HW + idx];
    out[BN*CN*TK + t] = pe[(size_t)c*HW + idx];
}

// ---------------- launch ----------------------------------------------------
extern "C" void kernel_launch(void* const* d_in, const int* in_sizes, int n_in,
                              void* d_out, int out_size){
    const float* x  = (const float*)d_in[0];
    const float* pe = (const float*)d_in[1];
    const float* w1 = (const float*)d_in[2];
    const float* b1 = (const float*)d_in[3];
    const float* w2 = (const float*)d_in[4];
    const float* b2 = (const float*)d_in[5];
    float* out = (float*)d_out;

    cudaFuncSetAttribute(kmma,   cudaFuncAttributeMaxDynamicSharedMemorySize, 3*STG_SZ);
    cudaFuncSetAttribute(k4_topk, cudaFuncAttributeMaxDynamicSharedMemorySize, 131072);

    dim3 gt((NPX + 31)/32, BN);
    t_half<<<gt, 256>>>(x);
    k0_wprep<<<(144*16*32*4 + 255)/256, 256>>>(w1, w2);

    dim3 gg(128, 4, BN);
    kmma<<<gg, 256, 3*STG_SZ>>>(b1);

    k2_conv1<<<(BN*HW)/256, 256>>>(b2, out);
    k3_boost<<<(BN*HW)/256, 256>>>();
    k4_topk<<<BN, 1024, 131072>>>();
    k5_gather<<<(BN*CN*TK + 255)/256, 256>>>(x, pe, out);
}

// round 14
// speedup vs baseline: 1.2455x; 1.2455x over previous
#include <cuda_runtime.h>
#include <cuda_fp16.h>
#include <cstdint>

#define NCLS 80
#define NCH  81
#define TK   100
#define BN   8
#define CN   256
#define HN   128
#define WN   128
#define HW   (HN*WN)
#define PP   130
#define NPX  (PP*PP)

// ---------------- scratch (device globals) ---------------------------------
__device__ __half g_xh[(size_t)BN*NPX*CN];   // NHWC padded, fp16-hi
__device__ __half g_xl[(size_t)BN*NPX*CN];   // NHWC padded, fp16-lo
// w1 in mma-fragment order: [k16 index][ogp(16)][lane(32)] -> uint4
__device__ uint4  g_wfh[73728];              // 144*16*32 uint4
__device__ uint4  g_wfl[73728];
// w2 in mma-fragment order: [k16(16)][n8(12)][lane(32)] -> uint2
__device__ uint2  g_w2fh[6144];
__device__ uint2  g_w2fl[6144];
__device__ __half g_yh[(size_t)BN*HW*CN];    // relu(conv3x3) fp16-hi, NHWC
__device__ __half g_yl[(size_t)BN*HW*CN];    // fp16-lo
__device__ float  g_pstar[BN*HW];
__device__ int    g_cls[BN*HW];
__device__ float  g_scores[BN*HW];
__device__ int    g_topidx[BN*TK];

// ---------------- PTX helpers ----------------------------------------------
__device__ __forceinline__ uint32_t smem_u32(const void* p){
    uint32_t a;
    asm("{ .reg .u64 t; cvta.to.shared.u64 t, %1; cvt.u32.u64 %0, t; }" : "=r"(a) : "l"(p));
    return a;
}
__device__ __forceinline__ void cpa16(uint32_t dst, const void* src){
    asm volatile("cp.async.cg.shared.global [%0], [%1], 16;" :: "r"(dst), "l"(src));
}
#define CP_COMMIT() asm volatile("cp.async.commit_group;" ::: "memory")
#define CP_WAIT1()  asm volatile("cp.async.wait_group 1;" ::: "memory")
#define CP_WAIT0()  asm volatile("cp.async.wait_group 0;" ::: "memory")

__device__ __forceinline__ void mma16816(float* d, const uint32_t* a, const uint32_t* b){
    asm volatile("mma.sync.aligned.m16n8k16.row.col.f32.f16.f16.f32 "
        "{%0,%1,%2,%3}, {%4,%5,%6,%7}, {%8,%9}, {%0,%1,%2,%3};"
        : "+f"(d[0]), "+f"(d[1]), "+f"(d[2]), "+f"(d[3])
        : "r"(a[0]), "r"(a[1]), "r"(a[2]), "r"(a[3]), "r"(b[0]), "r"(b[1]));
}
__device__ __forceinline__ void ldm4(uint32_t* r, uint32_t addr){
    asm volatile("ldmatrix.sync.aligned.m8n8.x4.shared.b16 {%0,%1,%2,%3}, [%4];"
        : "=r"(r[0]), "=r"(r[1]), "=r"(r[2]), "=r"(r[3]) : "r"(addr));
}

// ---------------- T0: NCHW -> padded NHWC fp16 hi/lo ------------------------
__global__ __launch_bounds__(256) void t_half(const float* __restrict__ x){
    __shared__ float s[256][33];
    const int b = blockIdx.y;
    const int px0 = blockIdx.x*32;
    const int tid = threadIdx.x;
    const int pxl = tid & 31, cg = tid >> 5;
    const int p = px0 + pxl;
    const int ph = p / PP, pw = p % PP;
    const bool in = (p < NPX) && ph >= 1 && ph <= 128 && pw >= 1 && pw <= 128;
    const float* xp = x + (size_t)b*CN*HW + (size_t)(ph-1)*WN + (pw-1);
    #pragma unroll 8
    for (int i=0;i<32;i++){
        int c = i*8 + cg;
        s[c][pxl] = in ? xp[(size_t)c*HW] : 0.f;
    }
    __syncthreads();
    for (int j=0;j<32;j++){
        int px = px0 + j;
        if (px >= NPX) break;
        float v  = s[tid][j];
        __half hi = __float2half_rn(v);
        __half lo = __float2half_rn(v - __half2float(hi));
        size_t o = ((size_t)b*NPX + px)*CN + tid;
        g_xh[o] = hi;
        g_xl[o] = lo;
    }
}

// ---------------- K0: weight prep (fragment order, w1 + w2) -----------------
__global__ void k0_wprep(const float* __restrict__ w1,
                         const float* __restrict__ w2){
    int t = blockIdx.x*256 + threadIdx.x;
    if (t < 144*16*32*4){
        int j    = t & 3;
        int l    = (t>>2) & 31;
        int ogp  = (t>>7) & 15;
        int k16  = t >> 11;
        int tap  = k16 >> 4;
        int oc = (ogp*2 + (j>>1))*8 + (l>>2);
        int k  = (k16 & 15)*16 + (j&1)*8 + (l&3)*2;
        float v0 = w1[((size_t)oc*CN + k  )*9 + tap];
        float v1 = w1[((size_t)oc*CN + k+1)*9 + tap];
        __half h0 = __float2half_rn(v0);
        __half h1 = __float2half_rn(v1);
        __half l0 = __float2half_rn(v0 - __half2float(h0));
        __half l1 = __float2half_rn(v1 - __half2float(h1));
        ((uint32_t*)g_wfh)[t] = (uint32_t)__half_as_ushort(h0) |
                                ((uint32_t)__half_as_ushort(h1) << 16);
        ((uint32_t*)g_wfl)[t] = (uint32_t)__half_as_ushort(l0) |
                                ((uint32_t)__half_as_ushort(l1) << 16);
    }
    // w2 fragments: u32 elements t2 < 16*12*32*2 = 12288
    if (t < 12288){
        int j   = t & 1;
        int l   = (t>>1) & 31;
        int r   = t >> 6;
        int gn  = r % 12;
        int k16 = r / 12;
        int oc  = gn*8 + (l>>2);
        int k   = k16*16 + j*8 + (l&3)*2;
        float v0 = (oc < NCH) ? w2[oc*CN + k]   : 0.f;
        float v1 = (oc < NCH) ? w2[oc*CN + k+1] : 0.f;
        __half h0 = __float2half_rn(v0);
        __half h1 = __float2half_rn(v1);
        __half l0 = __float2half_rn(v0 - __half2float(h0));
        __half l1 = __float2half_rn(v1 - __half2float(h1));
        uint32_t ph = (uint32_t)__half_as_ushort(h0) | ((uint32_t)__half_as_ushort(h1) << 16);
        uint32_t pl = (uint32_t)__half_as_ushort(l0) | ((uint32_t)__half_as_ushort(l1) << 16);
        int idx = (k16*12 + gn)*32 + l;
        if (j == 0){ g_w2fh[idx].x = ph; g_w2fl[idx].x = pl; }
        else       { g_w2fh[idx].y = ph; g_w2fl[idx].y = pl; }
    }
}

// ---------------- K1: conv3x3 via mma.sync fp16 split (R12 config) ----------
#define STG_SZ 32768u
#define AL_OFF 16384u

__global__ __launch_bounds__(256,2) void kmma(const float* __restrict__ b1){
    extern __shared__ __align__(16) char smem[];
    const uint32_t sb = smem_u32(smem);
    const int tid  = threadIdx.x;
    const int lane = tid & 31, wid = tid >> 5;
    const int wm = wid >> 2, wn = wid & 3;
    const int h  = blockIdx.x;
    const int ocb = blockIdx.y * 128;
    const int bb = blockIdx.z;

    const int lrow = tid >> 1, lhalf = tid & 1;
    const uint32_t fsw = (uint32_t)(lrow & 7);
    const int fc0 = 4*lhalf;

    auto load_stage = [&](int g, int buf){
        const int tap = g >> 2, kc = g & 3;
        const int ky = tap/3, kx = tap%3;
        const uint32_t sbase = sb + buf*STG_SZ;
        const size_t apix = (size_t)bb*NPX + (size_t)(h + ky)*PP + kx + lrow;
        const size_t aoff = apix*CN + kc*64 + fc0*8;
        #pragma unroll
        for (int i=0;i<4;i++){
            const uint32_t dst = (uint32_t)lrow*128u + (((uint32_t)(fc0+i)) ^ fsw)*16u;
            cpa16(sbase          + dst, g_xh + aoff + i*8);
            cpa16(sbase + AL_OFF + dst, g_xl + aoff + i*8);
        }
        CP_COMMIT();
    };

    float acc[4][4][4];
    #pragma unroll
    for (int mt=0;mt<4;mt++)
        #pragma unroll
        for (int nt=0;nt<4;nt++)
            #pragma unroll
            for (int q=0;q<4;q++) acc[mt][nt][q] = 0.f;

    load_stage(0, 0);
    load_stage(1, 1);

    const uint32_t rA  = (uint32_t)(lane & 15);
    const uint32_t sA  = (uint32_t)(lane & 7);
    const uint32_t cA0 = (uint32_t)(lane >> 4);
    const int ogp_base = blockIdx.y*8 + wn*2;

    for (int g=0; g<36; g++){
        const int buf = g % 3;
        CP_WAIT1();
        __syncthreads();
        if (g + 2 < 36) load_stage(g+2, (g+2)%3);

        const uint32_t sbase  = sb + buf*STG_SZ;
        const uint32_t aBaseH = sbase          + (uint32_t)(wm*64 + (int)rA)*128u;
        const uint32_t aBaseL = sbase + AL_OFF + (uint32_t)(wm*64 + (int)rA)*128u;

        #pragma unroll
        for (int q=0; q<4; q++){
            const int fb = ((g*4 + q)*16 + ogp_base)*32 + lane;
            const uint4 bq0 = __ldg(&g_wfh[fb]);
            const uint4 bq1 = __ldg(&g_wfh[fb + 32]);
            const uint4 cq0 = __ldg(&g_wfl[fb]);
            const uint4 cq1 = __ldg(&g_wfl[fb + 32]);
            uint32_t bh[4][2] = {{bq0.x,bq0.y},{bq0.z,bq0.w},{bq1.x,bq1.y},{bq1.z,bq1.w}};
            uint32_t bl[4][2] = {{cq0.x,cq0.y},{cq0.z,cq0.w},{cq1.x,cq1.y},{cq1.z,cq1.w}};

            const uint32_t gA = ((uint32_t)(q*2) + cA0) ^ sA;
            uint32_t ah[4][4], al[4][4];
            #pragma unroll
            for (int mt=0;mt<4;mt++){
                ldm4(ah[mt], aBaseH + (uint32_t)(mt*16)*128u + gA*16u);
                ldm4(al[mt], aBaseL + (uint32_t)(mt*16)*128u + gA*16u);
            }
            #pragma unroll
            for (int mt=0;mt<4;mt++)
                #pragma unroll
                for (int nt=0;nt<4;nt++){
                    mma16816(acc[mt][nt], ah[mt], bh[nt]);
                    mma16816(acc[mt][nt], ah[mt], bl[nt]);
                    mma16816(acc[mt][nt], al[mt], bh[nt]);
                }
        }
    }
    CP_WAIT0();

    // epilogue: bias + relu -> y fp16 hi/lo, NHWC
    #pragma unroll
    for (int nt=0;nt<4;nt++){
        const int cc = ocb + wn*32 + nt*8 + (lane & 3)*2;
        const float bz0 = b1[cc], bz1 = b1[cc+1];
        #pragma unroll
        for (int mt=0;mt<4;mt++){
            const int w = wm*64 + mt*16 + (lane >> 2);
            const size_t pix = (size_t)bb*HW + (size_t)h*WN + w;
            float f0 = fmaxf(acc[mt][nt][0] + bz0, 0.f);
            float f1 = fmaxf(acc[mt][nt][1] + bz1, 0.f);
            float f2 = fmaxf(acc[mt][nt][2] + bz0, 0.f);
            float f3 = fmaxf(acc[mt][nt][3] + bz1, 0.f);
            __half h0 = __float2half_rn(f0), h1 = __float2half_rn(f1);
            __half h2 = __float2half_rn(f2), h3 = __float2half_rn(f3);
            *(__half2*)&g_yh[pix*CN + cc]     = __halves2half2(h0, h1);
            *(__half2*)&g_yh[(pix+8)*CN + cc] = __halves2half2(h2, h3);
            *(__half2*)&g_yl[pix*CN + cc]     = __halves2half2(
                __float2half_rn(f0 - __half2float(h0)), __float2half_rn(f1 - __half2float(h1)));
            *(__half2*)&g_yl[(pix+8)*CN + cc] = __halves2half2(
                __float2half_rn(f2 - __half2float(h2)), __float2half_rn(f3 - __half2float(h3)));
        }
    }
}

// ---------------- K2: conv1x1 logits via mma (128px x 96oc CTA) -------------
// grid (128, 1, 8); 256 threads = 8 warps (2M x 4N), warp m64n24 (3 n8 groups).
// A: y fp16 hi/lo, 3-stage ring, 4 g-iters (64 cin each). B: g_w2f LDG.64.
__global__ __launch_bounds__(256,2) void kgemm2(const float* __restrict__ b2,
                                                float* __restrict__ out){
    extern __shared__ __align__(16) char smem[];
    const uint32_t sb = smem_u32(smem);
    const int tid  = threadIdx.x;
    const int lane = tid & 31, wid = tid >> 5;
    const int wm = wid >> 2, wn = wid & 3;
    const int pxb = blockIdx.x * 128;
    const int bb = blockIdx.z;

    const int lrow = tid >> 1, lhalf = tid & 1;
    const uint32_t fsw = (uint32_t)(lrow & 7);
    const int fc0 = 4*lhalf;

    auto load_stage = [&](int g, int buf){
        const uint32_t sbase = sb + buf*STG_SZ;
        const size_t apix = (size_t)bb*HW + pxb + lrow;
        const size_t aoff = apix*CN + g*64 + fc0*8;
        #pragma unroll
        for (int i=0;i<4;i++){
            const uint32_t dst = (uint32_t)lrow*128u + (((uint32_t)(fc0+i)) ^ fsw)*16u;
            cpa16(sbase          + dst, g_yh + aoff + i*8);
            cpa16(sbase + AL_OFF + dst, g_yl + aoff + i*8);
        }
        CP_COMMIT();
    };

    float acc[4][3][4];
    #pragma unroll
    for (int mt=0;mt<4;mt++)
        #pragma unroll
        for (int nt=0;nt<3;nt++)
            #pragma unroll
            for (int q=0;q<4;q++) acc[mt][nt][q] = 0.f;

    load_stage(0, 0);
    load_stage(1, 1);

    const uint32_t rA  = (uint32_t)(lane & 15);
    const uint32_t sA  = (uint32_t)(lane & 7);
    const uint32_t cA0 = (uint32_t)(lane >> 4);

    for (int g=0; g<4; g++){
        const int buf = g % 3;
        CP_WAIT1();
        __syncthreads();
        if (g + 2 < 4) load_stage(g+2, (g+2)%3);

        const uint32_t sbase  = sb + buf*STG_SZ;
        const uint32_t aBaseH = sbase          + (uint32_t)(wm*64 + (int)rA)*128u;
        const uint32_t aBaseL = sbase + AL_OFF + (uint32_t)(wm*64 + (int)rA)*128u;

        #pragma unroll
        for (int q=0; q<4; q++){
            const int k16 = g*4 + q;
            uint32_t bh[3][2], bl[3][2];
            #pragma unroll
            for (int nt=0;nt<3;nt++){
                const int fb = (k16*12 + wn*3 + nt)*32 + lane;
                uint2 u = __ldg(&g_w2fh[fb]); bh[nt][0]=u.x; bh[nt][1]=u.y;
                uint2 v = __ldg(&g_w2fl[fb]); bl[nt][0]=v.x; bl[nt][1]=v.y;
            }
            const uint32_t gA = ((uint32_t)(q*2) + cA0) ^ sA;
            uint32_t ah[4][4], al[4][4];
            #pragma unroll
            for (int mt=0;mt<4;mt++){
                ldm4(ah[mt], aBaseH + (uint32_t)(mt*16)*128u + gA*16u);
                ldm4(al[mt], aBaseL + (uint32_t)(mt*16)*128u + gA*16u);
            }
            #pragma unroll
            for (int mt=0;mt<4;mt++)
                #pragma unroll
                for (int nt=0;nt<3;nt++){
                    mma16816(acc[mt][nt], ah[mt], bh[nt]);
                    mma16816(acc[mt][nt], ah[mt], bl[nt]);
                    mma16816(acc[mt][nt], al[mt], bh[nt]);
                }
        }
    }
    CP_WAIT0();

    // epilogue: + bias -> logits in out (CHW per batch)
    float* lob = out + 409600 + (size_t)bb*NCH*HW;
    #pragma unroll
    for (int nt=0;nt<3;nt++){
        const int oc0 = wn*24 + nt*8 + (lane & 3)*2;
        const bool v0ok = (oc0 < NCH), v1ok = (oc0+1 < NCH);
        const float bz0 = v0ok ? b2[oc0] : 0.f;
        const float bz1 = v1ok ? b2[oc0+1] : 0.f;
        #pragma unroll
        for (int mt=0;mt<4;mt++){
            const int hw = pxb + wm*64 + mt*16 + (lane >> 2);
            if (v0ok){
                lob[(size_t)oc0*HW + hw]     = acc[mt][nt][0] + bz0;
                lob[(size_t)oc0*HW + hw + 8] = acc[mt][nt][2] + bz0;
            }
            if (v1ok){
                lob[(size_t)(oc0+1)*HW + hw]     = acc[mt][nt][1] + bz1;
                lob[(size_t)(oc0+1)*HW + hw + 8] = acc[mt][nt][3] + bz1;
            }
        }
    }
}

// ---------------- K2b: softmax stats from logits -----------------------------
__global__ __launch_bounds__(256) void k2b_stats(const float* __restrict__ out){
    const int gp = blockIdx.x*256 + threadIdx.x;
    const int b = gp >> 14, hw = gp & (HW-1);
    const float* lo = out + 409600 + (size_t)b*NCH*HW + hw;

    float m = -1e30f, best = -1e30f;
    int cls = 0;
    #pragma unroll
    for (int o=0;o<NCH;o++){
        float v = lo[(size_t)o*HW];
        m = fmaxf(m, v);
        if (o < NCLS && v > best){ best = v; cls = o; }
    }
    float s = 0.f;
    #pragma unroll
    for (int o=0;o<NCH;o++)
        s += __expf(lo[(size_t)o*HW] - m);

    g_pstar[gp] = __expf(best - m)/s;
    g_cls[gp]   = cls;
}

// ---------------- K3: local-max boost + score map --------------------------
__global__ void k3_boost(){
    const int gp = blockIdx.x*256 + threadIdx.x;
    const int b = gp>>14, hw = gp&(HW-1);
    const int h = hw>>7,  w  = hw&127;
    const float p = g_pstar[gp];
    const int   c = g_cls[gp];
    bool ok = (p >= 1e-6f);
    #pragma unroll
    for (int dy=-1; dy<=1; dy++)
        #pragma unroll
        for (int dx=-1; dx<=1; dx++){
            if (dy==0 && dx==0) continue;
            int nh = h+dy, nw = w+dx;
            if (nh<0 || nh>=HN || nw<0 || nw>=WN) continue;
            int n = (b<<14) + nh*WN + nw;
            if (g_cls[n]==c && p < g_pstar[n]) ok = false;
        }
    g_scores[gp] = p + (ok ? 1.f : 0.f);
}

// ---------------- K4: per-batch top-100 via bitonic sort -------------------
__global__ void k4_topk(){
    extern __shared__ unsigned long long sk[];
    const int N = HW;
    const int b = blockIdx.x, tid = threadIdx.x;
    for (int i=tid; i<N; i+=1024){
        unsigned sb2 = __float_as_uint(g_scores[(b<<14)+i]);
        sk[i] = ((unsigned long long)sb2<<32) | (unsigned)(0xFFFFFFFFu - (unsigned)i);
    }
    __syncthreads();
    for (int k=2; k<=N; k<<=1){
        for (int j=k>>1; j>0; j>>=1){
            for (int i=tid; i<N; i+=1024){
                int ixj = i^j;
                if (ixj > i){
                    unsigned long long a = sk[i], c = sk[ixj];
                    bool up = (i&k)==0;
                    if (up ? (a<c) : (a>c)){ sk[i]=c; sk[ixj]=a; }
                }
            }
            __syncthreads();
        }
    }
    if (tid < TK){
        unsigned low = (unsigned)sk[tid];
        g_topidx[b*TK + tid] = (int)(0xFFFFFFFFu - low);
    }
}

// ---------------- K5: gather proposals + pos embeddings --------------------
__global__ void k5_gather(const float* __restrict__ x,
                          const float* __restrict__ pe,
                          float* __restrict__ out){
    const int t = blockIdx.x*256 + threadIdx.x;
    if (t >= BN*CN*TK) return;
    const int k = t % TK;
    const int c = (t / TK) % CN;
    const int b = t / (TK*CN);
    const int idx = g_topidx[b*TK + k];
    out[t]            = x [(size_t)(b*CN + c)*HW + idx];
    out[BN*CN*TK + t] = pe[(size_t)c*HW + idx];
}

// ---------------- launch ----------------------------------------------------
extern "C" void kernel_launch(void* const* d_in, const int* in_sizes, int n_in,
                              void* d_out, int out_size){
    const float* x  = (const float*)d_in[0];
    const float* pe = (const float*)d_in[1];
    const float* w1 = (const float*)d_in[2];
    const float* b1 = (const float*)d_in[3];
    const float* w2 = (const float*)d_in[4];
    const float* b2 = (const float*)d_in[5];
    float* out = (float*)d_out;

    cudaFuncSetAttribute(kmma,   cudaFuncAttributeMaxDynamicSharedMemorySize, 3*STG_SZ);
    cudaFuncSetAttribute(kgemm2, cudaFuncAttributeMaxDynamicSharedMemorySize, 3*STG_SZ);
    cudaFuncSetAttribute(k4_topk, cudaFuncAttributeMaxDynamicSharedMemorySize, 131072);

    dim3 gt((NPX + 31)/32, BN);
    t_half<<<gt, 256>>>(x);
    k0_wprep<<<(144*16*32*4 + 255)/256, 256>>>(w1, w2);

    dim3 gg(128, 2, BN);
    kmma<<<gg, 256, 3*STG_SZ>>>(b1);

    dim3 g2(128, 1, BN);
    kgemm2<<<g2, 256, 3*STG_SZ>>>(b2, out);
    k2b_stats<<<(BN*HW)/256, 256>>>(out);
    k3_boost<<<(BN*HW)/256, 256>>>();
    k4_topk<<<BN, 1024, 131072>>>();
    k5_gather<<<(BN*CN*TK + 255)/256, 256>>>(x, pe, out);
}

// round 15
// speedup vs baseline: 1.3955x; 1.1205x over previous
#include <cuda_runtime.h>
#include <cuda_fp16.h>
#include <cstdint>

#define NCLS 80
#define NCH  81
#define TK   100
#define BN   8
#define CN   256
#define HN   128
#define WN   128
#define HW   (HN*WN)
#define PP   130
#define NPX  (PP*PP)

// ---------------- scratch (device globals) ---------------------------------
__device__ __half g_xh[(size_t)BN*NPX*CN];   // NHWC padded, fp16-hi
__device__ __half g_xl[(size_t)BN*NPX*CN];   // NHWC padded, fp16-lo
// w1 in mma-fragment order: [k16 index][ogp(16)][lane(32)] -> uint4
__device__ uint4  g_wfh[73728];              // 144*16*32 uint4
__device__ uint4  g_wfl[73728];
// w2 in mma-fragment order: [k16(16)][n8(12)][lane(32)] -> uint2
__device__ uint2  g_w2fh[6144];
__device__ uint2  g_w2fl[6144];
__device__ __half g_yh[(size_t)BN*HW*CN];    // relu(conv3x3) fp16-hi, NHWC
__device__ __half g_yl[(size_t)BN*HW*CN];    // fp16-lo
__device__ float  g_pstar[BN*HW];
__device__ int    g_cls[BN*HW];
__device__ float  g_scores[BN*HW];
__device__ unsigned long long g_ptop[BN*8*128];   // per-chunk top-128 keys
__device__ int    g_topidx[BN*TK];

// ---------------- PTX helpers ----------------------------------------------
__device__ __forceinline__ uint32_t smem_u32(const void* p){
    uint32_t a;
    asm("{ .reg .u64 t; cvta.to.shared.u64 t, %1; cvt.u32.u64 %0, t; }" : "=r"(a) : "l"(p));
    return a;
}
__device__ __forceinline__ void cpa16(uint32_t dst, const void* src){
    asm volatile("cp.async.cg.shared.global [%0], [%1], 16;" :: "r"(dst), "l"(src));
}
#define CP_COMMIT() asm volatile("cp.async.commit_group;" ::: "memory")
#define CP_WAIT1()  asm volatile("cp.async.wait_group 1;" ::: "memory")
#define CP_WAIT0()  asm volatile("cp.async.wait_group 0;" ::: "memory")

__device__ __forceinline__ void mma16816(float* d, const uint32_t* a, const uint32_t* b){
    asm volatile("mma.sync.aligned.m16n8k16.row.col.f32.f16.f16.f32 "
        "{%0,%1,%2,%3}, {%4,%5,%6,%7}, {%8,%9}, {%0,%1,%2,%3};"
        : "+f"(d[0]), "+f"(d[1]), "+f"(d[2]), "+f"(d[3])
        : "r"(a[0]), "r"(a[1]), "r"(a[2]), "r"(a[3]), "r"(b[0]), "r"(b[1]));
}
__device__ __forceinline__ void ldm4(uint32_t* r, uint32_t addr){
    asm volatile("ldmatrix.sync.aligned.m8n8.x4.shared.b16 {%0,%1,%2,%3}, [%4];"
        : "=r"(r[0]), "=r"(r[1]), "=r"(r[2]), "=r"(r[3]) : "r"(addr));
}

// ---------------- T0: NCHW -> padded NHWC fp16 hi/lo ------------------------
__global__ __launch_bounds__(256) void t_half(const float* __restrict__ x){
    __shared__ float s[256][33];
    const int b = blockIdx.y;
    const int px0 = blockIdx.x*32;
    const int tid = threadIdx.x;
    const int pxl = tid & 31, cg = tid >> 5;
    const int p = px0 + pxl;
    const int ph = p / PP, pw = p % PP;
    const bool in = (p < NPX) && ph >= 1 && ph <= 128 && pw >= 1 && pw <= 128;
    const float* xp = x + (size_t)b*CN*HW + (size_t)(ph-1)*WN + (pw-1);
    #pragma unroll 8
    for (int i=0;i<32;i++){
        int c = i*8 + cg;
        s[c][pxl] = in ? xp[(size_t)c*HW] : 0.f;
    }
    __syncthreads();
    for (int j=0;j<32;j++){
        int px = px0 + j;
        if (px >= NPX) break;
        float v  = s[tid][j];
        __half hi = __float2half_rn(v);
        __half lo = __float2half_rn(v - __half2float(hi));
        size_t o = ((size_t)b*NPX + px)*CN + tid;
        g_xh[o] = hi;
        g_xl[o] = lo;
    }
}

// ---------------- K0: weight prep (fragment order, w1 + w2) -----------------
__global__ void k0_wprep(const float* __restrict__ w1,
                         const float* __restrict__ w2){
    int t = blockIdx.x*256 + threadIdx.x;
    if (t < 144*16*32*4){
        int j    = t & 3;
        int l    = (t>>2) & 31;
        int ogp  = (t>>7) & 15;
        int k16  = t >> 11;
        int tap  = k16 >> 4;
        int oc = (ogp*2 + (j>>1))*8 + (l>>2);
        int k  = (k16 & 15)*16 + (j&1)*8 + (l&3)*2;
        float v0 = w1[((size_t)oc*CN + k  )*9 + tap];
        float v1 = w1[((size_t)oc*CN + k+1)*9 + tap];
        __half h0 = __float2half_rn(v0);
        __half h1 = __float2half_rn(v1);
        __half l0 = __float2half_rn(v0 - __half2float(h0));
        __half l1 = __float2half_rn(v1 - __half2float(h1));
        ((uint32_t*)g_wfh)[t] = (uint32_t)__half_as_ushort(h0) |
                                ((uint32_t)__half_as_ushort(h1) << 16);
        ((uint32_t*)g_wfl)[t] = (uint32_t)__half_as_ushort(l0) |
                                ((uint32_t)__half_as_ushort(l1) << 16);
    }
    if (t < 12288){
        int j   = t & 1;
        int l   = (t>>1) & 31;
        int r   = t >> 6;
        int gn  = r % 12;
        int k16 = r / 12;
        int oc  = gn*8 + (l>>2);
        int k   = k16*16 + j*8 + (l&3)*2;
        float v0 = (oc < NCH) ? w2[oc*CN + k]   : 0.f;
        float v1 = (oc < NCH) ? w2[oc*CN + k+1] : 0.f;
        __half h0 = __float2half_rn(v0);
        __half h1 = __float2half_rn(v1);
        __half l0 = __float2half_rn(v0 - __half2float(h0));
        __half l1 = __float2half_rn(v1 - __half2float(h1));
        uint32_t ph = (uint32_t)__half_as_ushort(h0) | ((uint32_t)__half_as_ushort(h1) << 16);
        uint32_t pl = (uint32_t)__half_as_ushort(l0) | ((uint32_t)__half_as_ushort(l1) << 16);
        int idx = (k16*12 + gn)*32 + l;
        if (j == 0){ g_w2fh[idx].x = ph; g_w2fl[idx].x = pl; }
        else       { g_w2fh[idx].y = ph; g_w2fl[idx].y = pl; }
    }
}

// ---------------- K1: conv3x3 via mma.sync fp16 split (R12 config) ----------
#define STG_SZ 32768u
#define AL_OFF 16384u

__global__ __launch_bounds__(256,2) void kmma(const float* __restrict__ b1){
    extern __shared__ __align__(16) char smem[];
    const uint32_t sb = smem_u32(smem);
    const int tid  = threadIdx.x;
    const int lane = tid & 31, wid = tid >> 5;
    const int wm = wid >> 2, wn = wid & 3;
    const int h  = blockIdx.x;
    const int ocb = blockIdx.y * 128;
    const int bb = blockIdx.z;

    const int lrow = tid >> 1, lhalf = tid & 1;
    const uint32_t fsw = (uint32_t)(lrow & 7);
    const int fc0 = 4*lhalf;

    auto load_stage = [&](int g, int buf){
        const int tap = g >> 2, kc = g & 3;
        const int ky = tap/3, kx = tap%3;
        const uint32_t sbase = sb + buf*STG_SZ;
        const size_t apix = (size_t)bb*NPX + (size_t)(h + ky)*PP + kx + lrow;
        const size_t aoff = apix*CN + kc*64 + fc0*8;
        #pragma unroll
        for (int i=0;i<4;i++){
            const uint32_t dst = (uint32_t)lrow*128u + (((uint32_t)(fc0+i)) ^ fsw)*16u;
            cpa16(sbase          + dst, g_xh + aoff + i*8);
            cpa16(sbase + AL_OFF + dst, g_xl + aoff + i*8);
        }
        CP_COMMIT();
    };

    float acc[4][4][4];
    #pragma unroll
    for (int mt=0;mt<4;mt++)
        #pragma unroll
        for (int nt=0;nt<4;nt++)
            #pragma unroll
            for (int q=0;q<4;q++) acc[mt][nt][q] = 0.f;

    load_stage(0, 0);
    load_stage(1, 1);

    const uint32_t rA  = (uint32_t)(lane & 15);
    const uint32_t sA  = (uint32_t)(lane & 7);
    const uint32_t cA0 = (uint32_t)(lane >> 4);
    const int ogp_base = blockIdx.y*8 + wn*2;

    for (int g=0; g<36; g++){
        const int buf = g % 3;
        CP_WAIT1();
        __syncthreads();
        if (g + 2 < 36) load_stage(g+2, (g+2)%3);

        const uint32_t sbase  = sb + buf*STG_SZ;
        const uint32_t aBaseH = sbase          + (uint32_t)(wm*64 + (int)rA)*128u;
        const uint32_t aBaseL = sbase + AL_OFF + (uint32_t)(wm*64 + (int)rA)*128u;

        #pragma unroll
        for (int q=0; q<4; q++){
            const int fb = ((g*4 + q)*16 + ogp_base)*32 + lane;
            const uint4 bq0 = __ldg(&g_wfh[fb]);
            const uint4 bq1 = __ldg(&g_wfh[fb + 32]);
            const uint4 cq0 = __ldg(&g_wfl[fb]);
            const uint4 cq1 = __ldg(&g_wfl[fb + 32]);
            uint32_t bh[4][2] = {{bq0.x,bq0.y},{bq0.z,bq0.w},{bq1.x,bq1.y},{bq1.z,bq1.w}};
            uint32_t bl[4][2] = {{cq0.x,cq0.y},{cq0.z,cq0.w},{cq1.x,cq1.y},{cq1.z,cq1.w}};

            const uint32_t gA = ((uint32_t)(q*2) + cA0) ^ sA;
            uint32_t ah[4][4], al[4][4];
            #pragma unroll
            for (int mt=0;mt<4;mt++){
                ldm4(ah[mt], aBaseH + (uint32_t)(mt*16)*128u + gA*16u);
                ldm4(al[mt], aBaseL + (uint32_t)(mt*16)*128u + gA*16u);
            }
            #pragma unroll
            for (int mt=0;mt<4;mt++)
                #pragma unroll
                for (int nt=0;nt<4;nt++){
                    mma16816(acc[mt][nt], ah[mt], bh[nt]);
                    mma16816(acc[mt][nt], ah[mt], bl[nt]);
                    mma16816(acc[mt][nt], al[mt], bh[nt]);
                }
        }
    }
    CP_WAIT0();

    // epilogue: bias + relu -> y fp16 hi/lo, NHWC
    #pragma unroll
    for (int nt=0;nt<4;nt++){
        const int cc = ocb + wn*32 + nt*8 + (lane & 3)*2;
        const float bz0 = b1[cc], bz1 = b1[cc+1];
        #pragma unroll
        for (int mt=0;mt<4;mt++){
            const int w = wm*64 + mt*16 + (lane >> 2);
            const size_t pix = (size_t)bb*HW + (size_t)h*WN + w;
            float f0 = fmaxf(acc[mt][nt][0] + bz0, 0.f);
            float f1 = fmaxf(acc[mt][nt][1] + bz1, 0.f);
            float f2 = fmaxf(acc[mt][nt][2] + bz0, 0.f);
            float f3 = fmaxf(acc[mt][nt][3] + bz1, 0.f);
            __half h0 = __float2half_rn(f0), h1 = __float2half_rn(f1);
            __half h2 = __float2half_rn(f2), h3 = __float2half_rn(f3);
            *(__half2*)&g_yh[pix*CN + cc]     = __halves2half2(h0, h1);
            *(__half2*)&g_yh[(pix+8)*CN + cc] = __halves2half2(h2, h3);
            *(__half2*)&g_yl[pix*CN + cc]     = __halves2half2(
                __float2half_rn(f0 - __half2float(h0)), __float2half_rn(f1 - __half2float(h1)));
            *(__half2*)&g_yl[(pix+8)*CN + cc] = __halves2half2(
                __float2half_rn(f2 - __half2float(h2)), __float2half_rn(f3 - __half2float(h3)));
        }
    }
}

// ---------------- K2: conv1x1 logits via mma + fused softmax stats ----------
// grid (128, 1, 8); 256 threads = 8 warps (2M x 4N), warp m64n24.
// After mainloop, logits staged in (dead) smem ring and stats computed in-CTA.
#define SLOG_W 85

__global__ __launch_bounds__(256,2) void kgemm2(const float* __restrict__ b2,
                                                float* __restrict__ out){
    extern __shared__ __align__(16) char smem[];
    const uint32_t sb = smem_u32(smem);
    const int tid  = threadIdx.x;
    const int lane = tid & 31, wid = tid >> 5;
    const int wm = wid >> 2, wn = wid & 3;
    const int pxb = blockIdx.x * 128;
    const int bb = blockIdx.z;

    const int lrow = tid >> 1, lhalf = tid & 1;
    const uint32_t fsw = (uint32_t)(lrow & 7);
    const int fc0 = 4*lhalf;

    auto load_stage = [&](int g, int buf){
        const uint32_t sbase = sb + buf*STG_SZ;
        const size_t apix = (size_t)bb*HW + pxb + lrow;
        const size_t aoff = apix*CN + g*64 + fc0*8;
        #pragma unroll
        for (int i=0;i<4;i++){
            const uint32_t dst = (uint32_t)lrow*128u + (((uint32_t)(fc0+i)) ^ fsw)*16u;
            cpa16(sbase          + dst, g_yh + aoff + i*8);
            cpa16(sbase + AL_OFF + dst, g_yl + aoff + i*8);
        }
        CP_COMMIT();
    };

    float acc[4][3][4];
    #pragma unroll
    for (int mt=0;mt<4;mt++)
        #pragma unroll
        for (int nt=0;nt<3;nt++)
            #pragma unroll
            for (int q=0;q<4;q++) acc[mt][nt][q] = 0.f;

    load_stage(0, 0);
    load_stage(1, 1);

    const uint32_t rA  = (uint32_t)(lane & 15);
    const uint32_t sA  = (uint32_t)(lane & 7);
    const uint32_t cA0 = (uint32_t)(lane >> 4);

    for (int g=0; g<4; g++){
        const int buf = g % 3;
        CP_WAIT1();
        __syncthreads();
        if (g + 2 < 4) load_stage(g+2, (g+2)%3);

        const uint32_t sbase  = sb + buf*STG_SZ;
        const uint32_t aBaseH = sbase          + (uint32_t)(wm*64 + (int)rA)*128u;
        const uint32_t aBaseL = sbase + AL_OFF + (uint32_t)(wm*64 + (int)rA)*128u;

        #pragma unroll
        for (int q=0; q<4; q++){
            const int k16 = g*4 + q;
            uint32_t bh[3][2], bl[3][2];
            #pragma unroll
            for (int nt=0;nt<3;nt++){
                const int fb = (k16*12 + wn*3 + nt)*32 + lane;
                uint2 u = __ldg(&g_w2fh[fb]); bh[nt][0]=u.x; bh[nt][1]=u.y;
                uint2 v = __ldg(&g_w2fl[fb]); bl[nt][0]=v.x; bl[nt][1]=v.y;
            }
            const uint32_t gA = ((uint32_t)(q*2) + cA0) ^ sA;
            uint32_t ah[4][4], al[4][4];
            #pragma unroll
            for (int mt=0;mt<4;mt++){
                ldm4(ah[mt], aBaseH + (uint32_t)(mt*16)*128u + gA*16u);
                ldm4(al[mt], aBaseL + (uint32_t)(mt*16)*128u + gA*16u);
            }
            #pragma unroll
            for (int mt=0;mt<4;mt++)
                #pragma unroll
                for (int nt=0;nt<3;nt++){
                    mma16816(acc[mt][nt], ah[mt], bh[nt]);
                    mma16816(acc[mt][nt], ah[mt], bl[nt]);
                    mma16816(acc[mt][nt], al[mt], bh[nt]);
                }
        }
    }
    CP_WAIT0();
    __syncthreads();                       // ring dead; reuse smem for logits

    float* slog = (float*)smem;            // [128 px][SLOG_W]
    float* lob = out + 409600 + (size_t)bb*NCH*HW;
    #pragma unroll
    for (int nt=0;nt<3;nt++){
        const int oc0 = wn*24 + nt*8 + (lane & 3)*2;
        const bool v0ok = (oc0 < NCH), v1ok = (oc0+1 < NCH);
        const float bz0 = v0ok ? b2[oc0] : 0.f;
        const float bz1 = v1ok ? b2[oc0+1] : 0.f;
        #pragma unroll
        for (int mt=0;mt<4;mt++){
            const int r  = wm*64 + mt*16 + (lane >> 2);
            const int hw = pxb + r;
            float L0 = acc[mt][nt][0] + bz0;
            float L1 = acc[mt][nt][1] + bz1;
            float L2 = acc[mt][nt][2] + bz0;
            float L3 = acc[mt][nt][3] + bz1;
            if (v0ok){
                lob[(size_t)oc0*HW + hw]     = L0;
                lob[(size_t)oc0*HW + hw + 8] = L2;
                slog[r*SLOG_W + oc0]       = L0;
                slog[(r+8)*SLOG_W + oc0]   = L2;
            }
            if (v1ok){
                lob[(size_t)(oc0+1)*HW + hw]     = L1;
                lob[(size_t)(oc0+1)*HW + hw + 8] = L3;
                slog[r*SLOG_W + oc0+1]     = L1;
                slog[(r+8)*SLOG_W + oc0+1] = L3;
            }
        }
    }
    __syncthreads();

    if (tid < 128){
        const float* lr = slog + tid*SLOG_W;
        float m = -1e30f, best = -1e30f;
        int cls = 0;
        #pragma unroll
        for (int o=0;o<NCH;o++){
            float v = lr[o];
            m = fmaxf(m, v);
            if (o < NCLS && v > best){ best = v; cls = o; }
        }
        float s = 0.f;
        #pragma unroll
        for (int o=0;o<NCH;o++) s += __expf(lr[o] - m);
        const int gp = (bb<<14) + pxb + tid;
        g_pstar[gp] = __expf(best - m)/s;
        g_cls[gp]   = cls;
    }
}

// ---------------- K3: local-max boost + score map --------------------------
__global__ void k3_boost(){
    const int gp = blockIdx.x*256 + threadIdx.x;
    const int b = gp>>14, hw = gp&(HW-1);
    const int h = hw>>7,  w  = hw&127;
    const float p = g_pstar[gp];
    const int   c = g_cls[gp];
    bool ok = (p >= 1e-6f);
    #pragma unroll
    for (int dy=-1; dy<=1; dy++)
        #pragma unroll
        for (int dx=-1; dx<=1; dx++){
            if (dy==0 && dx==0) continue;
            int nh = h+dy, nw = w+dx;
            if (nh<0 || nh>=HN || nw<0 || nw>=WN) continue;
            int n = (b<<14) + nh*WN + nw;
            if (g_cls[n]==c && p < g_pstar[n]) ok = false;
        }
    g_scores[gp] = p + (ok ? 1.f : 0.f);
}

// ---------------- K4a: per-chunk top-128 (64 CTAs) -------------------------
__global__ void k4a_topk(){
    __shared__ unsigned long long sk[2048];
    const int b = blockIdx.y, c = blockIdx.x, tid = threadIdx.x;
    const int base = (b<<14) + c*2048;
    for (int i=tid; i<2048; i+=256){
        unsigned sb2 = __float_as_uint(g_scores[base+i]);
        sk[i] = ((unsigned long long)sb2<<32) | (unsigned)(0xFFFFFFFFu - (unsigned)(base+i));
    }
    __syncthreads();
    for (int k=2; k<=2048; k<<=1){
        for (int j=k>>1; j>0; j>>=1){
            for (int i=tid; i<2048; i+=256){
                int ixj = i^j;
                if (ixj > i){
                    unsigned long long a = sk[i], d = sk[ixj];
                    bool up = (i&k)==0;
                    if (up ? (a<d) : (a>d)){ sk[i]=d; sk[ixj]=a; }
                }
            }
            __syncthreads();
        }
    }
    if (tid < 128)
        g_ptop[(b*8 + c)*128 + tid] = sk[tid];
}

// ---------------- K4b: merge 8x128 -> top-100 (8 CTAs) ----------------------
__global__ void k4b_topk(){
    __shared__ unsigned long long sk[1024];
    const int b = blockIdx.x, tid = threadIdx.x;
    for (int i=tid; i<1024; i+=256)
        sk[i] = g_ptop[b*1024 + i];
    __syncthreads();
    for (int k=2; k<=1024; k<<=1){
        for (int j=k>>1; j>0; j>>=1){
            for (int i=tid; i<1024; i+=256){
                int ixj = i^j;
                if (ixj > i){
                    unsigned long long a = sk[i], d = sk[ixj];
                    bool up = (i&k)==0;
                    if (up ? (a<d) : (a>d)){ sk[i]=d; sk[ixj]=a; }
                }
            }
            __syncthreads();
        }
    }
    if (tid < TK){
        unsigned low = (unsigned)sk[tid];
        g_topidx[b*TK + tid] = (int)((0xFFFFFFFFu - low) & 0x3FFFu);
    }
}

// ---------------- K5: gather proposals + pos embeddings --------------------
__global__ void k5_gather(const float* __restrict__ x,
                          const float* __restrict__ pe,
                          float* __restrict__ out){
    const int t = blockIdx.x*256 + threadIdx.x;
    if (t >= BN*CN*TK) return;
    const int k = t % TK;
    const int c = (t / TK) % CN;
    const int b = t / (TK*CN);
    const int idx = g_topidx[b*TK + k];
    out[t]            = x [(size_t)(b*CN + c)*HW + idx];
    out[BN*CN*TK + t] = pe[(size_t)c*HW + idx];
}

// ---------------- launch ----------------------------------------------------
extern "C" void kernel_launch(void* const* d_in, const int* in_sizes, int n_in,
                              void* d_out, int out_size){
    const float* x  = (const float*)d_in[0];
    const float* pe = (const float*)d_in[1];
    const float* w1 = (const float*)d_in[2];
    const float* b1 = (const float*)d_in[3];
    const float* w2 = (const float*)d_in[4];
    const float* b2 = (const float*)d_in[5];
    float* out = (float*)d_out;

    cudaFuncSetAttribute(kmma,   cudaFuncAttributeMaxDynamicSharedMemorySize, 3*STG_SZ);
    cudaFuncSetAttribute(kgemm2, cudaFuncAttributeMaxDynamicSharedMemorySize, 3*STG_SZ);

    dim3 gt((NPX + 31)/32, BN);
    t_half<<<gt, 256>>>(x);
    k0_wprep<<<(144*16*32*4 + 255)/256, 256>>>(w1, w2);

    dim3 gg(128, 2, BN);
    kmma<<<gg, 256, 3*STG_SZ>>>(b1);

    dim3 g2(128, 1, BN);
    kgemm2<<<g2, 256, 3*STG_SZ>>>(b2, out);
    k3_boost<<<(BN*HW)/256, 256>>>();
    dim3 g4(8, BN);
    k4a_topk<<<g4, 256>>>();
    k4b_topk<<<BN, 256>>>();
    k5_gather<<<(BN*CN*TK + 255)/256, 256>>>(x, pe, out);
}

// round 16
// speedup vs baseline: 1.5442x; 1.1066x over previous
#include <cuda_runtime.h>
#include <cuda_fp16.h>
#include <cstdint>

#define NCLS 80
#define NCH  81
#define TK   100
#define BN   8
#define CN   256
#define HN   128
#define WN   128
#define HW   (HN*WN)
#define PP   130
#define NPX  (PP*PP)

// ---------------- scratch (device globals) ---------------------------------
__device__ __half g_xh[(size_t)BN*NPX*CN];   // NHWC padded, fp16-hi
__device__ __half g_xl[(size_t)BN*NPX*CN];   // NHWC padded, fp16-lo
// w1 in mma-fragment order: [k16 index][ogp(16)][lane(32)] -> uint4
__device__ uint4  g_wfh[73728];              // 144*16*32 uint4
__device__ uint4  g_wfl[73728];
// w2 in mma-fragment order: [k16(16)][n8(12)][lane(32)] -> uint2
__device__ uint2  g_w2fh[6144];
__device__ uint2  g_w2fl[6144];
__device__ __half g_yh[(size_t)BN*HW*CN];    // relu(conv3x3) fp16-hi, NHWC
__device__ __half g_yl[(size_t)BN*HW*CN];    // fp16-lo
__device__ float  g_pstar[BN*HW];
__device__ int    g_cls[BN*HW];
__device__ float  g_scores[BN*HW];
__device__ unsigned long long g_ptop[BN*8*128];   // per-chunk top-128 keys
__device__ int    g_topidx[BN*TK];

// ---------------- PTX helpers ----------------------------------------------
__device__ __forceinline__ uint32_t smem_u32(const void* p){
    uint32_t a;
    asm("{ .reg .u64 t; cvta.to.shared.u64 t, %1; cvt.u32.u64 %0, t; }" : "=r"(a) : "l"(p));
    return a;
}
__device__ __forceinline__ void cpa16(uint32_t dst, const void* src){
    asm volatile("cp.async.cg.shared.global [%0], [%1], 16;" :: "r"(dst), "l"(src));
}
#define CP_COMMIT() asm volatile("cp.async.commit_group;" ::: "memory")
#define CP_WAIT1()  asm volatile("cp.async.wait_group 1;" ::: "memory")
#define CP_WAIT0()  asm volatile("cp.async.wait_group 0;" ::: "memory")
#define BARH(id)    asm volatile("bar.sync %0, 128;" :: "r"(id) : "memory")

__device__ __forceinline__ void mma16816(float* d, const uint32_t* a, const uint32_t* b){
    asm volatile("mma.sync.aligned.m16n8k16.row.col.f32.f16.f16.f32 "
        "{%0,%1,%2,%3}, {%4,%5,%6,%7}, {%8,%9}, {%0,%1,%2,%3};"
        : "+f"(d[0]), "+f"(d[1]), "+f"(d[2]), "+f"(d[3])
        : "r"(a[0]), "r"(a[1]), "r"(a[2]), "r"(a[3]), "r"(b[0]), "r"(b[1]));
}
__device__ __forceinline__ void ldm4(uint32_t* r, uint32_t addr){
    asm volatile("ldmatrix.sync.aligned.m8n8.x4.shared.b16 {%0,%1,%2,%3}, [%4];"
        : "=r"(r[0]), "=r"(r[1]), "=r"(r[2]), "=r"(r[3]) : "r"(addr));
}

// ---------------- T0: NCHW -> padded NHWC fp16 hi/lo ------------------------
__global__ __launch_bounds__(256) void t_half(const float* __restrict__ x){
    __shared__ float s[256][33];
    const int b = blockIdx.y;
    const int px0 = blockIdx.x*32;
    const int tid = threadIdx.x;
    const int pxl = tid & 31, cg = tid >> 5;
    const int p = px0 + pxl;
    const int ph = p / PP, pw = p % PP;
    const bool in = (p < NPX) && ph >= 1 && ph <= 128 && pw >= 1 && pw <= 128;
    const float* xp = x + (size_t)b*CN*HW + (size_t)(ph-1)*WN + (pw-1);
    #pragma unroll 8
    for (int i=0;i<32;i++){
        int c = i*8 + cg;
        s[c][pxl] = in ? xp[(size_t)c*HW] : 0.f;
    }
    __syncthreads();
    for (int j=0;j<32;j++){
        int px = px0 + j;
        if (px >= NPX) break;
        float v  = s[tid][j];
        __half hi = __float2half_rn(v);
        __half lo = __float2half_rn(v - __half2float(hi));
        size_t o = ((size_t)b*NPX + px)*CN + tid;
        g_xh[o] = hi;
        g_xl[o] = lo;
    }
}

// ---------------- K0: weight prep (fragment order, w1 + w2) -----------------
__global__ void k0_wprep(const float* __restrict__ w1,
                         const float* __restrict__ w2){
    int t = blockIdx.x*256 + threadIdx.x;
    if (t < 144*16*32*4){
        int j    = t & 3;
        int l    = (t>>2) & 31;
        int ogp  = (t>>7) & 15;
        int k16  = t >> 11;
        int tap  = k16 >> 4;
        int oc = (ogp*2 + (j>>1))*8 + (l>>2);
        int k  = (k16 & 15)*16 + (j&1)*8 + (l&3)*2;
        float v0 = w1[((size_t)oc*CN + k  )*9 + tap];
        float v1 = w1[((size_t)oc*CN + k+1)*9 + tap];
        __half h0 = __float2half_rn(v0);
        __half h1 = __float2half_rn(v1);
        __half l0 = __float2half_rn(v0 - __half2float(h0));
        __half l1 = __float2half_rn(v1 - __half2float(h1));
        ((uint32_t*)g_wfh)[t] = (uint32_t)__half_as_ushort(h0) |
                                ((uint32_t)__half_as_ushort(h1) << 16);
        ((uint32_t*)g_wfl)[t] = (uint32_t)__half_as_ushort(l0) |
                                ((uint32_t)__half_as_ushort(l1) << 16);
    }
    if (t < 12288){
        int j   = t & 1;
        int l   = (t>>1) & 31;
        int r   = t >> 6;
        int gn  = r % 12;
        int k16 = r / 12;
        int oc  = gn*8 + (l>>2);
        int k   = k16*16 + j*8 + (l&3)*2;
        float v0 = (oc < NCH) ? w2[oc*CN + k]   : 0.f;
        float v1 = (oc < NCH) ? w2[oc*CN + k+1] : 0.f;
        __half h0 = __float2half_rn(v0);
        __half h1 = __float2half_rn(v1);
        __half l0 = __float2half_rn(v0 - __half2float(h0));
        __half l1 = __float2half_rn(v1 - __half2float(h1));
        uint32_t ph = (uint32_t)__half_as_ushort(h0) | ((uint32_t)__half_as_ushort(h1) << 16);
        uint32_t pl = (uint32_t)__half_as_ushort(l0) | ((uint32_t)__half_as_ushort(l1) << 16);
        int idx = (k16*12 + gn)*32 + l;
        if (j == 0){ g_w2fh[idx].x = ph; g_w2fl[idx].x = pl; }
        else       { g_w2fh[idx].y = ph; g_w2fl[idx].y = pl; }
    }
}

// ---------------- K1: conv3x3 via mma.sync fp16 split ------------------------
// grid (128 h, 2 octile, 8 b); 256 threads = 8 warps (2M x 4N), warp m64n32.
// Split-barrier halves: tid<128 (wm0) fills & consumes rows 0-63; tid>=128
// (wm1) rows 64-127 — bar.sync {1,2},128 instead of __syncthreads.
// Stage fills spread across the q-loop (2 cpa16/thread/q, 1 commit/stage).
#define STG_SZ 32768u
#define AL_OFF 16384u

__global__ __launch_bounds__(256,2) void kmma(const float* __restrict__ b1){
    extern __shared__ __align__(16) char smem[];
    const uint32_t sb = smem_u32(smem);
    const int tid  = threadIdx.x;
    const int lane = tid & 31, wid = tid >> 5;
    const int wm = wid >> 2, wn = wid & 3;
    const int h  = blockIdx.x;
    const int ocb = blockIdx.y * 128;
    const int bb = blockIdx.z;

    const int lrow = tid >> 1, lhalf = tid & 1;
    const uint32_t fsw = (uint32_t)(lrow & 7);
    const int fc0 = 4*lhalf;

    // full-stage fill (prologue only)
    auto load_stage_full = [&](int g, int buf){
        const int tap = g >> 2, kc = g & 3;
        const int ky = tap/3, kx = tap%3;
        const uint32_t sbase = sb + buf*STG_SZ;
        const size_t apix = (size_t)bb*NPX + (size_t)(h + ky)*PP + kx + lrow;
        const size_t aoff = apix*CN + kc*64 + fc0*8;
        #pragma unroll
        for (int i=0;i<4;i++){
            const uint32_t dst = (uint32_t)lrow*128u + (((uint32_t)(fc0+i)) ^ fsw)*16u;
            cpa16(sbase          + dst, g_xh + aoff + i*8);
            cpa16(sbase + AL_OFF + dst, g_xl + aoff + i*8);
        }
        CP_COMMIT();
    };

    float acc[4][4][4];
    #pragma unroll
    for (int mt=0;mt<4;mt++)
        #pragma unroll
        for (int nt=0;nt<4;nt++)
            #pragma unroll
            for (int q=0;q<4;q++) acc[mt][nt][q] = 0.f;

    load_stage_full(0, 0);
    load_stage_full(1, 1);

    const uint32_t rA  = (uint32_t)(lane & 15);
    const uint32_t sA  = (uint32_t)(lane & 7);
    const uint32_t cA0 = (uint32_t)(lane >> 4);
    const int ogp_base = blockIdx.y*8 + wn*2;
    const int barid = 1 + wm;

    for (int g=0; g<36; g++){
        const int buf = g % 3;
        CP_WAIT1();
        BARH(barid);

        // next-next stage fill coords (issued 2 cpa16 per q below)
        const bool pf = (g + 2 < 36);
        const int g2 = g + 2;
        const int tap2 = g2 >> 2, kc2 = g2 & 3;
        const uint32_t pbase = sb + (g2 % 3)*STG_SZ;
        const size_t paoff = ((size_t)bb*NPX
            + (size_t)(h + tap2/3)*PP + (tap2%3) + lrow)*CN + kc2*64 + fc0*8;

        const uint32_t sbase  = sb + buf*STG_SZ;
        const uint32_t aBaseH = sbase          + (uint32_t)(wm*64 + (int)rA)*128u;
        const uint32_t aBaseL = sbase + AL_OFF + (uint32_t)(wm*64 + (int)rA)*128u;

        #pragma unroll
        for (int q=0; q<4; q++){
            if (pf){
                const uint32_t dst = (uint32_t)lrow*128u + (((uint32_t)(fc0+q)) ^ fsw)*16u;
                cpa16(pbase          + dst, g_xh + paoff + q*8);
                cpa16(pbase + AL_OFF + dst, g_xl + paoff + q*8);
            }
            const int fb = ((g*4 + q)*16 + ogp_base)*32 + lane;
            const uint4 bq0 = __ldg(&g_wfh[fb]);
            const uint4 bq1 = __ldg(&g_wfh[fb + 32]);
            const uint4 cq0 = __ldg(&g_wfl[fb]);
            const uint4 cq1 = __ldg(&g_wfl[fb + 32]);
            uint32_t bh[4][2] = {{bq0.x,bq0.y},{bq0.z,bq0.w},{bq1.x,bq1.y},{bq1.z,bq1.w}};
            uint32_t bl[4][2] = {{cq0.x,cq0.y},{cq0.z,cq0.w},{cq1.x,cq1.y},{cq1.z,cq1.w}};

            const uint32_t gA = ((uint32_t)(q*2) + cA0) ^ sA;
            uint32_t ah[4][4], al[4][4];
            #pragma unroll
            for (int mt=0;mt<4;mt++){
                ldm4(ah[mt], aBaseH + (uint32_t)(mt*16)*128u + gA*16u);
                ldm4(al[mt], aBaseL + (uint32_t)(mt*16)*128u + gA*16u);
            }
            #pragma unroll
            for (int mt=0;mt<4;mt++)
                #pragma unroll
                for (int nt=0;nt<4;nt++){
                    mma16816(acc[mt][nt], ah[mt], bh[nt]);
                    mma16816(acc[mt][nt], ah[mt], bl[nt]);
                    mma16816(acc[mt][nt], al[mt], bh[nt]);
                }
        }
        if (pf) CP_COMMIT();
    }
    CP_WAIT0();

    // epilogue: bias + relu -> y fp16 hi/lo, NHWC
    #pragma unroll
    for (int nt=0;nt<4;nt++){
        const int cc = ocb + wn*32 + nt*8 + (lane & 3)*2;
        const float bz0 = b1[cc], bz1 = b1[cc+1];
        #pragma unroll
        for (int mt=0;mt<4;mt++){
            const int w = wm*64 + mt*16 + (lane >> 2);
            const size_t pix = (size_t)bb*HW + (size_t)h*WN + w;
            float f0 = fmaxf(acc[mt][nt][0] + bz0, 0.f);
            float f1 = fmaxf(acc[mt][nt][1] + bz1, 0.f);
            float f2 = fmaxf(acc[mt][nt][2] + bz0, 0.f);
            float f3 = fmaxf(acc[mt][nt][3] + bz1, 0.f);
            __half h0 = __float2half_rn(f0), h1 = __float2half_rn(f1);
            __half h2 = __float2half_rn(f2), h3 = __float2half_rn(f3);
            *(__half2*)&g_yh[pix*CN + cc]     = __halves2half2(h0, h1);
            *(__half2*)&g_yh[(pix+8)*CN + cc] = __halves2half2(h2, h3);
            *(__half2*)&g_yl[pix*CN + cc]     = __halves2half2(
                __float2half_rn(f0 - __half2float(h0)), __float2half_rn(f1 - __half2float(h1)));
            *(__half2*)&g_yl[(pix+8)*CN + cc] = __halves2half2(
                __float2half_rn(f2 - __half2float(h2)), __float2half_rn(f3 - __half2float(h3)));
        }
    }
}

// ---------------- K2: conv1x1 logits via mma + fused softmax stats ----------
#define SLOG_W 85

__global__ __launch_bounds__(256,2) void kgemm2(const float* __restrict__ b2,
                                                float* __restrict__ out){
    extern __shared__ __align__(16) char smem[];
    const uint32_t sb = smem_u32(smem);
    const int tid  = threadIdx.x;
    const int lane = tid & 31, wid = tid >> 5;
    const int wm = wid >> 2, wn = wid & 3;
    const int pxb = blockIdx.x * 128;
    const int bb = blockIdx.z;

    const int lrow = tid >> 1, lhalf = tid & 1;
    const uint32_t fsw = (uint32_t)(lrow & 7);
    const int fc0 = 4*lhalf;

    auto load_stage = [&](int g, int buf){
        const uint32_t sbase = sb + buf*STG_SZ;
        const size_t apix = (size_t)bb*HW + pxb + lrow;
        const size_t aoff = apix*CN + g*64 + fc0*8;
        #pragma unroll
        for (int i=0;i<4;i++){
            const uint32_t dst = (uint32_t)lrow*128u + (((uint32_t)(fc0+i)) ^ fsw)*16u;
            cpa16(sbase          + dst, g_yh + aoff + i*8);
            cpa16(sbase + AL_OFF + dst, g_yl + aoff + i*8);
        }
        CP_COMMIT();
    };

    float acc[4][3][4];
    #pragma unroll
    for (int mt=0;mt<4;mt++)
        #pragma unroll
        for (int nt=0;nt<3;nt++)
            #pragma unroll
            for (int q=0;q<4;q++) acc[mt][nt][q] = 0.f;

    load_stage(0, 0);
    load_stage(1, 1);

    const uint32_t rA  = (uint32_t)(lane & 15);
    const uint32_t sA  = (uint32_t)(lane & 7);
    const uint32_t cA0 = (uint32_t)(lane >> 4);

    for (int g=0; g<4; g++){
        const int buf = g % 3;
        CP_WAIT1();
        __syncthreads();
        if (g + 2 < 4) load_stage(g+2, (g+2)%3);

        const uint32_t sbase  = sb + buf*STG_SZ;
        const uint32_t aBaseH = sbase          + (uint32_t)(wm*64 + (int)rA)*128u;
        const uint32_t aBaseL = sbase + AL_OFF + (uint32_t)(wm*64 + (int)rA)*128u;

        #pragma unroll
        for (int q=0; q<4; q++){
            const int k16 = g*4 + q;
            uint32_t bh[3][2], bl[3][2];
            #pragma unroll
            for (int nt=0;nt<3;nt++){
                const int fb = (k16*12 + wn*3 + nt)*32 + lane;
                uint2 u = __ldg(&g_w2fh[fb]); bh[nt][0]=u.x; bh[nt][1]=u.y;
                uint2 v = __ldg(&g_w2fl[fb]); bl[nt][0]=v.x; bl[nt][1]=v.y;
            }
            const uint32_t gA = ((uint32_t)(q*2) + cA0) ^ sA;
            uint32_t ah[4][4], al[4][4];
            #pragma unroll
            for (int mt=0;mt<4;mt++){
                ldm4(ah[mt], aBaseH + (uint32_t)(mt*16)*128u + gA*16u);
                ldm4(al[mt], aBaseL + (uint32_t)(mt*16)*128u + gA*16u);
            }
            #pragma unroll
            for (int mt=0;mt<4;mt++)
                #pragma unroll
                for (int nt=0;nt<3;nt++){
                    mma16816(acc[mt][nt], ah[mt], bh[nt]);
                    mma16816(acc[mt][nt], ah[mt], bl[nt]);
                    mma16816(acc[mt][nt], al[mt], bh[nt]);
                }
        }
    }
    CP_WAIT0();
    __syncthreads();                       // ring dead; reuse smem for logits

    float* slog = (float*)smem;            // [128 px][SLOG_W]
    float* lob = out + 409600 + (size_t)bb*NCH*HW;
    #pragma unroll
    for (int nt=0;nt<3;nt++){
        const int oc0 = wn*24 + nt*8 + (lane & 3)*2;
        const bool v0ok = (oc0 < NCH), v1ok = (oc0+1 < NCH);
        const float bz0 = v0ok ? b2[oc0] : 0.f;
        const float bz1 = v1ok ? b2[oc0+1] : 0.f;
        #pragma unroll
        for (int mt=0;mt<4;mt++){
            const int r  = wm*64 + mt*16 + (lane >> 2);
            const int hw = pxb + r;
            float L0 = acc[mt][nt][0] + bz0;
            float L1 = acc[mt][nt][1] + bz1;
            float L2 = acc[mt][nt][2] + bz0;
            float L3 = acc[mt][nt][3] + bz1;
            if (v0ok){
                lob[(size_t)oc0*HW + hw]     = L0;
                lob[(size_t)oc0*HW + hw + 8] = L2;
                slog[r*SLOG_W + oc0]       = L0;
                slog[(r+8)*SLOG_W + oc0]   = L2;
            }
            if (v1ok){
                lob[(size_t)(oc0+1)*HW + hw]     = L1;
                lob[(size_t)(oc0+1)*HW + hw + 8] = L3;
                slog[r*SLOG_W + oc0+1]     = L1;
                slog[(r+8)*SLOG_W + oc0+1] = L3;
            }
        }
    }
    __syncthreads();

    if (tid < 128){
        const float* lr = slog + tid*SLOG_W;
        float m = -1e30f, best = -1e30f;
        int cls = 0;
        #pragma unroll
        for (int o=0;o<NCH;o++){
            float v = lr[o];
            m = fmaxf(m, v);
            if (o < NCLS && v > best){ best = v; cls = o; }
        }
        float s = 0.f;
        #pragma unroll
        for (int o=0;o<NCH;o++) s += __expf(lr[o] - m);
        const int gp = (bb<<14) + pxb + tid;
        g_pstar[gp] = __expf(best - m)/s;
        g_cls[gp]   = cls;
    }
}

// ---------------- K3: local-max boost + score map --------------------------
__global__ void k3_boost(){
    const int gp = blockIdx.x*256 + threadIdx.x;
    const int b = gp>>14, hw = gp&(HW-1);
    const int h = hw>>7,  w  = hw&127;
    const float p = g_pstar[gp];
    const int   c = g_cls[gp];
    bool ok = (p >= 1e-6f);
    #pragma unroll
    for (int dy=-1; dy<=1; dy++)
        #pragma unroll
        for (int dx=-1; dx<=1; dx++){
            if (dy==0 && dx==0) continue;
            int nh = h+dy, nw = w+dx;
            if (nh<0 || nh>=HN || nw<0 || nw>=WN) continue;
            int n = (b<<14) + nh*WN + nw;
            if (g_cls[n]==c && p < g_pstar[n]) ok = false;
        }
    g_scores[gp] = p + (ok ? 1.f : 0.f);
}

// ---------------- K4a: per-chunk top-128 (64 CTAs) -------------------------
__global__ void k4a_topk(){
    __shared__ unsigned long long sk[2048];
    const int b = blockIdx.y, c = blockIdx.x, tid = threadIdx.x;
    const int base = (b<<14) + c*2048;
    for (int i=tid; i<2048; i+=256){
        unsigned sb2 = __float_as_uint(g_scores[base+i]);
        sk[i] = ((unsigned long long)sb2<<32) | (unsigned)(0xFFFFFFFFu - (unsigned)(base+i));
    }
    __syncthreads();
    for (int k=2; k<=2048; k<<=1){
        for (int j=k>>1; j>0; j>>=1){
            for (int i=tid; i<2048; i+=256){
                int ixj = i^j;
                if (ixj > i){
                    unsigned long long a = sk[i], d = sk[ixj];
                    bool up = (i&k)==0;
                    if (up ? (a<d) : (a>d)){ sk[i]=d; sk[ixj]=a; }
                }
            }
            __syncthreads();
        }
    }
    if (tid < 128)
        g_ptop[(b*8 + c)*128 + tid] = sk[tid];
}

// ---------------- K4b: merge 8x128 -> top-100 (8 CTAs) ----------------------
__global__ void k4b_topk(){
    __shared__ unsigned long long sk[1024];
    const int b = blockIdx.x, tid = threadIdx.x;
    for (int i=tid; i<1024; i+=256)
        sk[i] = g_ptop[b*1024 + i];
    __syncthreads();
    for (int k=2; k<=1024; k<<=1){
        for (int j=k>>1; j>0; j>>=1){
            for (int i=tid; i<1024; i+=256){
                int ixj = i^j;
                if (ixj > i){
                    unsigned long long a = sk[i], d = sk[ixj];
                    bool up = (i&k)==0;
                    if (up ? (a<d) : (a>d)){ sk[i]=d; sk[ixj]=a; }
                }
            }
            __syncthreads();
        }
    }
    if (tid < TK){
        unsigned low = (unsigned)sk[tid];
        g_topidx[b*TK + tid] = (int)((0xFFFFFFFFu - low) & 0x3FFFu);
    }
}

// ---------------- K5: gather proposals + pos embeddings --------------------
__global__ void k5_gather(const float* __restrict__ x,
                          const float* __restrict__ pe,
                          float* __restrict__ out){
    const int t = blockIdx.x*256 + threadIdx.x;
    if (t >= BN*CN*TK) return;
    const int k = t % TK;
    const int c = (t / TK) % CN;
    const int b = t / (TK*CN);
    const int idx = g_topidx[b*TK + k];
    out[t]            = x [(size_t)(b*CN + c)*HW + idx];
    out[BN*CN*TK + t] = pe[(size_t)c*HW + idx];
}

// ---------------- launch ----------------------------------------------------
extern "C" void kernel_launch(void* const* d_in, const int* in_sizes, int n_in,
                              void* d_out, int out_size){
    const float* x  = (const float*)d_in[0];
    const float* pe = (const float*)d_in[1];
    const float* w1 = (const float*)d_in[2];
    const float* b1 = (const float*)d_in[3];
    const float* w2 = (const float*)d_in[4];
    const float* b2 = (const float*)d_in[5];
    float* out = (float*)d_out;

    cudaFuncSetAttribute(kmma,   cudaFuncAttributeMaxDynamicSharedMemorySize, 3*STG_SZ);
    cudaFuncSetAttribute(kgemm2, cudaFuncAttributeMaxDynamicSharedMemorySize, 3*STG_SZ);

    dim3 gt((NPX + 31)/32, BN);
    t_half<<<gt, 256>>>(x);
    k0_wprep<<<(144*16*32*4 + 255)/256, 256>>>(w1, w2);

    dim3 gg(128, 2, BN);
    kmma<<<gg, 256, 3*STG_SZ>>>(b1);

    dim3 g2(128, 1, BN);
    kgemm2<<<g2, 256, 3*STG_SZ>>>(b2, out);
    k3_boost<<<(BN*HW)/256, 256>>>();
    dim3 g4(8, BN);
    k4a_topk<<<g4, 256>>>();
    k4b_topk<<<BN, 256>>>();
    k5_gather<<<(BN*CN*TK + 255)/256, 256>>>(x, pe, out);
}

// round 17
// speedup vs baseline: 1.5713x; 1.0175x over previous
#include <cuda_runtime.h>
#include <cuda_fp16.h>
#include <cstdint>

#define NCLS 80
#define NCH  81
#define TK   100
#define BN   8
#define CN   256
#define HN   128
#define WN   128
#define HW   (HN*WN)
#define PP   130
#define NPX  (PP*PP)

// ---------------- scratch (device globals) ---------------------------------
__device__ __half g_xh[(size_t)BN*NPX*CN];   // NHWC padded, fp16-hi
__device__ __half g_xl[(size_t)BN*NPX*CN];   // NHWC padded, fp16-lo
// w1 in mma-fragment order: [k16 index][ogp(16)][lane(32)] -> uint4
__device__ uint4  g_wfh[73728];              // 144*16*32 uint4
__device__ uint4  g_wfl[73728];
// w2 in mma-fragment order: [k16(16)][n8(12)][lane(32)] -> uint2
__device__ uint2  g_w2fh[6144];
__device__ uint2  g_w2fl[6144];
__device__ __half g_yh[(size_t)BN*HW*CN];    // relu(conv3x3) fp16-hi, NHWC
__device__ __half g_yl[(size_t)BN*HW*CN];    // fp16-lo
__device__ float  g_pstar[BN*HW];
__device__ int    g_cls[BN*HW];
__device__ float  g_scores[BN*HW];
__device__ unsigned long long g_ptop[BN*8*128];   // per-chunk top-128 keys
__device__ int    g_topidx[BN*TK];

// ---------------- PTX helpers ----------------------------------------------
__device__ __forceinline__ uint32_t smem_u32(const void* p){
    uint32_t a;
    asm("{ .reg .u64 t; cvta.to.shared.u64 t, %1; cvt.u32.u64 %0, t; }" : "=r"(a) : "l"(p));
    return a;
}
__device__ __forceinline__ void cpa16(uint32_t dst, const void* src){
    asm volatile("cp.async.cg.shared.global [%0], [%1], 16;" :: "r"(dst), "l"(src));
}
#define CP_COMMIT() asm volatile("cp.async.commit_group;" ::: "memory")
#define CP_WAIT1()  asm volatile("cp.async.wait_group 1;" ::: "memory")
#define CP_WAIT0()  asm volatile("cp.async.wait_group 0;" ::: "memory")
#define BARH(id)    asm volatile("bar.sync %0, 128;" :: "r"(id) : "memory")

__device__ __forceinline__ void mma16816(float* d, const uint32_t* a, const uint32_t* b){
    asm volatile("mma.sync.aligned.m16n8k16.row.col.f32.f16.f16.f32 "
        "{%0,%1,%2,%3}, {%4,%5,%6,%7}, {%8,%9}, {%0,%1,%2,%3};"
        : "+f"(d[0]), "+f"(d[1]), "+f"(d[2]), "+f"(d[3])
        : "r"(a[0]), "r"(a[1]), "r"(a[2]), "r"(a[3]), "r"(b[0]), "r"(b[1]));
}
__device__ __forceinline__ void ldm4(uint32_t* r, uint32_t addr){
    asm volatile("ldmatrix.sync.aligned.m8n8.x4.shared.b16 {%0,%1,%2,%3}, [%4];"
        : "=r"(r[0]), "=r"(r[1]), "=r"(r[2]), "=r"(r[3]) : "r"(addr));
}

// ---------------- T0: NCHW -> padded NHWC fp16 hi/lo ------------------------
__global__ __launch_bounds__(256) void t_half(const float* __restrict__ x){
    __shared__ float s[256][33];
    const int b = blockIdx.y;
    const int px0 = blockIdx.x*32;
    const int tid = threadIdx.x;
    const int pxl = tid & 31, cg = tid >> 5;
    const int p = px0 + pxl;
    const int ph = p / PP, pw = p % PP;
    const bool in = (p < NPX) && ph >= 1 && ph <= 128 && pw >= 1 && pw <= 128;
    const float* xp = x + (size_t)b*CN*HW + (size_t)(ph-1)*WN + (pw-1);
    #pragma unroll 8
    for (int i=0;i<32;i++){
        int c = i*8 + cg;
        s[c][pxl] = in ? xp[(size_t)c*HW] : 0.f;
    }
    __syncthreads();
    for (int j=0;j<32;j++){
        int px = px0 + j;
        if (px >= NPX) break;
        float v  = s[tid][j];
        __half hi = __float2half_rn(v);
        __half lo = __float2half_rn(v - __half2float(hi));
        size_t o = ((size_t)b*NPX + px)*CN + tid;
        g_xh[o] = hi;
        g_xl[o] = lo;
    }
}

// ---------------- K0: weight prep (fragment order, w1 + w2) -----------------
__global__ void k0_wprep(const float* __restrict__ w1,
                         const float* __restrict__ w2){
    int t = blockIdx.x*256 + threadIdx.x;
    if (t < 144*16*32*4){
        int j    = t & 3;
        int l    = (t>>2) & 31;
        int ogp  = (t>>7) & 15;
        int k16  = t >> 11;
        int tap  = k16 >> 4;
        int oc = (ogp*2 + (j>>1))*8 + (l>>2);
        int k  = (k16 & 15)*16 + (j&1)*8 + (l&3)*2;
        float v0 = w1[((size_t)oc*CN + k  )*9 + tap];
        float v1 = w1[((size_t)oc*CN + k+1)*9 + tap];
        __half h0 = __float2half_rn(v0);
        __half h1 = __float2half_rn(v1);
        __half l0 = __float2half_rn(v0 - __half2float(h0));
        __half l1 = __float2half_rn(v1 - __half2float(h1));
        ((uint32_t*)g_wfh)[t] = (uint32_t)__half_as_ushort(h0) |
                                ((uint32_t)__half_as_ushort(h1) << 16);
        ((uint32_t*)g_wfl)[t] = (uint32_t)__half_as_ushort(l0) |
                                ((uint32_t)__half_as_ushort(l1) << 16);
    }
    if (t < 12288){
        int j   = t & 1;
        int l   = (t>>1) & 31;
        int r   = t >> 6;
        int gn  = r % 12;
        int k16 = r / 12;
        int oc  = gn*8 + (l>>2);
        int k   = k16*16 + j*8 + (l&3)*2;
        float v0 = (oc < NCH) ? w2[oc*CN + k]   : 0.f;
        float v1 = (oc < NCH) ? w2[oc*CN + k+1] : 0.f;
        __half h0 = __float2half_rn(v0);
        __half h1 = __float2half_rn(v1);
        __half l0 = __float2half_rn(v0 - __half2float(h0));
        __half l1 = __float2half_rn(v1 - __half2float(h1));
        uint32_t ph = (uint32_t)__half_as_ushort(h0) | ((uint32_t)__half_as_ushort(h1) << 16);
        uint32_t pl = (uint32_t)__half_as_ushort(l0) | ((uint32_t)__half_as_ushort(l1) << 16);
        int idx = (k16*12 + gn)*32 + l;
        if (j == 0){ g_w2fh[idx].x = ph; g_w2fl[idx].x = pl; }
        else       { g_w2fh[idx].y = ph; g_w2fl[idx].y = pl; }
    }
}

// ---------------- K1: conv3x3 via mma.sync fp16 split ------------------------
// grid (128 h, 2 octile, 8 b); 256 threads = 8 warps (2M x 4N), warp m64n32.
// Stage = (ky,kc): 130 pixels x 64 cin, stored once; kx shifts resolved by
// ldmatrix row offset. 12 stages (vs 36) -> 3x less cp.async traffic.
// Rows 64,65 duplicated into both half-regions (66 rows/half, 132 total) so
// split-barrier halves keep fill==consume ownership. Ring 3 x 33KB = 99KB.
#define STG_SZ  33792u
#define AL_OFF  16896u

__global__ __launch_bounds__(256,2) void kmma(const float* __restrict__ b1){
    extern __shared__ __align__(16) char smem[];
    const uint32_t sb = smem_u32(smem);
    const int tid  = threadIdx.x;
    const int lane = tid & 31, wid = tid >> 5;
    const int wm = wid >> 2, wn = wid & 3;
    const int htid = tid & 127, half = tid >> 7;
    const int h  = blockIdx.x;
    const int ocb = blockIdx.y * 128;
    const int bb = blockIdx.z;

    // fill unit u (0..263 per half): row_in = u>>2 (0..65), cpair = u&3
    auto fill_unit = [&](int u, int ky, int kc, uint32_t pbase){
        const int row_in = u >> 2, cpair = u & 3;
        const int srow = half*66 + row_in;                 // stage row 0..131
        const int c0 = 2*cpair;
        const size_t src = ((size_t)bb*NPX + (size_t)(h + ky)*PP
                          + half*64 + row_in)*CN + kc*64 + c0*8;
        const uint32_t key = (uint32_t)(srow & 7);
        const uint32_t d0 = (uint32_t)srow*128u + (((uint32_t)c0  ) ^ key)*16u;
        const uint32_t d1 = (uint32_t)srow*128u + (((uint32_t)c0+1u) ^ key)*16u;
        cpa16(pbase          + d0, g_xh + src);
        cpa16(pbase          + d1, g_xh + src + 8);
        cpa16(pbase + AL_OFF + d0, g_xl + src);
        cpa16(pbase + AL_OFF + d1, g_xl + src + 8);
    };
    auto load_stage_full = [&](int s, int buf){
        const int ky = s >> 2, kc = s & 3;
        const uint32_t pbase = sb + buf*STG_SZ;
        for (int u = htid; u < 264; u += 128)
            fill_unit(u, ky, kc, pbase);
        CP_COMMIT();
    };

    float acc[4][4][4];
    #pragma unroll
    for (int mt=0;mt<4;mt++)
        #pragma unroll
        for (int nt=0;nt<4;nt++)
            #pragma unroll
            for (int q=0;q<4;q++) acc[mt][nt][q] = 0.f;

    load_stage_full(0, 0);
    load_stage_full(1, 1);

    const uint32_t rA  = (uint32_t)(lane & 15);
    const uint32_t cA0 = (uint32_t)(lane >> 4);
    const int ogp_base = blockIdx.y*8 + wn*2;
    const int barid = 1 + wm;
    const int aRow0 = wm*66 + (int)rA;       // + mt*16 + kx

    for (int s=0; s<12; s++){
        const int buf = s % 3;
        const int ky = s >> 2, kc = s & 3;
        CP_WAIT1();
        BARH(barid);

        const bool pf = (s + 2 < 12);
        const int s2 = s + 2;
        const int ky2 = s2 >> 2, kc2 = s2 & 3;
        const uint32_t pbase = sb + (s2 % 3)*STG_SZ;

        const uint32_t sbase = sb + buf*STG_SZ;

        #pragma unroll
        for (int kx=0; kx<3; kx++){
            if (pf && htid < 88)
                fill_unit(kx*88 + htid, ky2, kc2, pbase);

            const uint32_t sAx = (uint32_t)((2*wm + (int)rA + kx) & 7);
            const int tap = ky*3 + kx;
            #pragma unroll
            for (int q=0; q<4; q++){
                const int k16 = tap*16 + kc*4 + q;
                const int fb = (k16*16 + ogp_base)*32 + lane;
                const uint4 bq0 = __ldg(&g_wfh[fb]);
                const uint4 bq1 = __ldg(&g_wfh[fb + 32]);
                const uint4 cq0 = __ldg(&g_wfl[fb]);
                const uint4 cq1 = __ldg(&g_wfl[fb + 32]);
                uint32_t bh[4][2] = {{bq0.x,bq0.y},{bq0.z,bq0.w},{bq1.x,bq1.y},{bq1.z,bq1.w}};
                uint32_t bl[4][2] = {{cq0.x,cq0.y},{cq0.z,cq0.w},{cq1.x,cq1.y},{cq1.z,cq1.w}};

                const uint32_t gA = ((uint32_t)(q*2) + cA0) ^ sAx;
                uint32_t ah[4][4], al[4][4];
                #pragma unroll
                for (int mt=0;mt<4;mt++){
                    const uint32_t rowb = (uint32_t)(aRow0 + mt*16 + kx)*128u + gA*16u;
                    ldm4(ah[mt], sbase          + rowb);
                    ldm4(al[mt], sbase + AL_OFF + rowb);
                }
                #pragma unroll
                for (int mt=0;mt<4;mt++)
                    #pragma unroll
                    for (int nt=0;nt<4;nt++){
                        mma16816(acc[mt][nt], ah[mt], bh[nt]);
                        mma16816(acc[mt][nt], ah[mt], bl[nt]);
                        mma16816(acc[mt][nt], al[mt], bh[nt]);
                    }
            }
        }
        if (pf) CP_COMMIT();
    }
    CP_WAIT0();

    // epilogue: bias + relu -> y fp16 hi/lo, NHWC
    #pragma unroll
    for (int nt=0;nt<4;nt++){
        const int cc = ocb + wn*32 + nt*8 + (lane & 3)*2;
        const float bz0 = b1[cc], bz1 = b1[cc+1];
        #pragma unroll
        for (int mt=0;mt<4;mt++){
            const int w = wm*64 + mt*16 + (lane >> 2);
            const size_t pix = (size_t)bb*HW + (size_t)h*WN + w;
            float f0 = fmaxf(acc[mt][nt][0] + bz0, 0.f);
            float f1 = fmaxf(acc[mt][nt][1] + bz1, 0.f);
            float f2 = fmaxf(acc[mt][nt][2] + bz0, 0.f);
            float f3 = fmaxf(acc[mt][nt][3] + bz1, 0.f);
            __half h0 = __float2half_rn(f0), h1 = __float2half_rn(f1);
            __half h2 = __float2half_rn(f2), h3 = __float2half_rn(f3);
            *(__half2*)&g_yh[pix*CN + cc]     = __halves2half2(h0, h1);
            *(__half2*)&g_yh[(pix+8)*CN + cc] = __halves2half2(h2, h3);
            *(__half2*)&g_yl[pix*CN + cc]     = __halves2half2(
                __float2half_rn(f0 - __half2float(h0)), __float2half_rn(f1 - __half2float(h1)));
            *(__half2*)&g_yl[(pix+8)*CN + cc] = __halves2half2(
                __float2half_rn(f2 - __half2float(h2)), __float2half_rn(f3 - __half2float(h3)));
        }
    }
}

// ---------------- K2: conv1x1 logits via mma + fused softmax stats ----------
#define STG2_SZ 32768u
#define AL2_OFF 16384u
#define SLOG_W 85

__global__ __launch_bounds__(256,2) void kgemm2(const float* __restrict__ b2,
                                                float* __restrict__ out){
    extern __shared__ __align__(16) char smem[];
    const uint32_t sb = smem_u32(smem);
    const int tid  = threadIdx.x;
    const int lane = tid & 31, wid = tid >> 5;
    const int wm = wid >> 2, wn = wid & 3;
    const int pxb = blockIdx.x * 128;
    const int bb = blockIdx.z;

    const int lrow = tid >> 1, lhalf = tid & 1;
    const uint32_t fsw = (uint32_t)(lrow & 7);
    const int fc0 = 4*lhalf;

    auto load_stage = [&](int g, int buf){
        const uint32_t sbase = sb + buf*STG2_SZ;
        const size_t apix = (size_t)bb*HW + pxb + lrow;
        const size_t aoff = apix*CN + g*64 + fc0*8;
        #pragma unroll
        for (int i=0;i<4;i++){
            const uint32_t dst = (uint32_t)lrow*128u + (((uint32_t)(fc0+i)) ^ fsw)*16u;
            cpa16(sbase           + dst, g_yh + aoff + i*8);
            cpa16(sbase + AL2_OFF + dst, g_yl + aoff + i*8);
        }
        CP_COMMIT();
    };

    float acc[4][3][4];
    #pragma unroll
    for (int mt=0;mt<4;mt++)
        #pragma unroll
        for (int nt=0;nt<3;nt++)
            #pragma unroll
            for (int q=0;q<4;q++) acc[mt][nt][q] = 0.f;

    load_stage(0, 0);
    load_stage(1, 1);

    const uint32_t rA  = (uint32_t)(lane & 15);
    const uint32_t sA  = (uint32_t)(lane & 7);
    const uint32_t cA0 = (uint32_t)(lane >> 4);

    for (int g=0; g<4; g++){
        const int buf = g % 3;
        CP_WAIT1();
        __syncthreads();
        if (g + 2 < 4) load_stage(g+2, (g+2)%3);

        const uint32_t sbase  = sb + buf*STG2_SZ;
        const uint32_t aBaseH = sbase           + (uint32_t)(wm*64 + (int)rA)*128u;
        const uint32_t aBaseL = sbase + AL2_OFF + (uint32_t)(wm*64 + (int)rA)*128u;

        #pragma unroll
        for (int q=0; q<4; q++){
            const int k16 = g*4 + q;
            uint32_t bh[3][2], bl[3][2];
            #pragma unroll
            for (int nt=0;nt<3;nt++){
                const int fb = (k16*12 + wn*3 + nt)*32 + lane;
                uint2 u = __ldg(&g_w2fh[fb]); bh[nt][0]=u.x; bh[nt][1]=u.y;
                uint2 v = __ldg(&g_w2fl[fb]); bl[nt][0]=v.x; bl[nt][1]=v.y;
            }
            const uint32_t gA = ((uint32_t)(q*2) + cA0) ^ sA;
            uint32_t ah[4][4], al[4][4];
            #pragma unroll
            for (int mt=0;mt<4;mt++){
                ldm4(ah[mt], aBaseH + (uint32_t)(mt*16)*128u + gA*16u);
                ldm4(al[mt], aBaseL + (uint32_t)(mt*16)*128u + gA*16u);
            }
            #pragma unroll
            for (int mt=0;mt<4;mt++)
                #pragma unroll
                for (int nt=0;nt<3;nt++){
                    mma16816(acc[mt][nt], ah[mt], bh[nt]);
                    mma16816(acc[mt][nt], ah[mt], bl[nt]);
                    mma16816(acc[mt][nt], al[mt], bh[nt]);
                }
        }
    }
    CP_WAIT0();
    __syncthreads();                       // ring dead; reuse smem for logits

    float* slog = (float*)smem;            // [128 px][SLOG_W]
    float* lob = out + 409600 + (size_t)bb*NCH*HW;
    #pragma unroll
    for (int nt=0;nt<3;nt++){
        const int oc0 = wn*24 + nt*8 + (lane & 3)*2;
        const bool v0ok = (oc0 < NCH), v1ok = (oc0+1 < NCH);
        const float bz0 = v0ok ? b2[oc0] : 0.f;
        const float bz1 = v1ok ? b2[oc0+1] : 0.f;
        #pragma unroll
        for (int mt=0;mt<4;mt++){
            const int r  = wm*64 + mt*16 + (lane >> 2);
            const int hw = pxb + r;
            float L0 = acc[mt][nt][0] + bz0;
            float L1 = acc[mt][nt][1] + bz1;
            float L2 = acc[mt][nt][2] + bz0;
            float L3 = acc[mt][nt][3] + bz1;
            if (v0ok){
                lob[(size_t)oc0*HW + hw]     = L0;
                lob[(size_t)oc0*HW + hw + 8] = L2;
                slog[r*SLOG_W + oc0]       = L0;
                slog[(r+8)*SLOG_W + oc0]   = L2;
            }
            if (v1ok){
                lob[(size_t)(oc0+1)*HW + hw]     = L1;
                lob[(size_t)(oc0+1)*HW + hw + 8] = L3;
                slog[r*SLOG_W + oc0+1]     = L1;
                slog[(r+8)*SLOG_W + oc0+1] = L3;
            }
        }
    }
    __syncthreads();

    if (tid < 128){
        const float* lr = slog + tid*SLOG_W;
        float m = -1e30f, best = -1e30f;
        int cls = 0;
        #pragma unroll
        for (int o=0;o<NCH;o++){
            float v = lr[o];
            m = fmaxf(m, v);
            if (o < NCLS && v > best){ best = v; cls = o; }
        }
        float s = 0.f;
        #pragma unroll
        for (int o=0;o<NCH;o++) s += __expf(lr[o] - m);
        const int gp = (bb<<14) + pxb + tid;
        g_pstar[gp] = __expf(best - m)/s;
        g_cls[gp]   = cls;
    }
}

// ---------------- K3: local-max boost + score map --------------------------
__global__ void k3_boost(){
    const int gp = blockIdx.x*256 + threadIdx.x;
    const int b = gp>>14, hw = gp&(HW-1);
    const int h = hw>>7,  w  = hw&127;
    const float p = g_pstar[gp];
    const int   c = g_cls[gp];
    bool ok = (p >= 1e-6f);
    #pragma unroll
    for (int dy=-1; dy<=1; dy++)
        #pragma unroll
        for (int dx=-1; dx<=1; dx++){
            if (dy==0 && dx==0) continue;
            int nh = h+dy, nw = w+dx;
            if (nh<0 || nh>=HN || nw<0 || nw>=WN) continue;
            int n = (b<<14) + nh*WN + nw;
            if (g_cls[n]==c && p < g_pstar[n]) ok = false;
        }
    g_scores[gp] = p + (ok ? 1.f : 0.f);
}

// ---------------- K4a: per-chunk top-128 (64 CTAs) -------------------------
__global__ void k4a_topk(){
    __shared__ unsigned long long sk[2048];
    const int b = blockIdx.y, c = blockIdx.x, tid = threadIdx.x;
    const int base = (b<<14) + c*2048;
    for (int i=tid; i<2048; i+=256){
        unsigned sb2 = __float_as_uint(g_scores[base+i]);
        sk[i] = ((unsigned long long)sb2<<32) | (unsigned)(0xFFFFFFFFu - (unsigned)(base+i));
    }
    __syncthreads();
    for (int k=2; k<=2048; k<<=1){
        for (int j=k>>1; j>0; j>>=1){
            for (int i=tid; i<2048; i+=256){
                int ixj = i^j;
                if (ixj > i){
                    unsigned long long a = sk[i], d = sk[ixj];
                    bool up = (i&k)==0;
                    if (up ? (a<d) : (a>d)){ sk[i]=d; sk[ixj]=a; }
                }
            }
            __syncthreads();
        }
    }
    if (tid < 128)
        g_ptop[(b*8 + c)*128 + tid] = sk[tid];
}

// ---------------- K4b: merge 8x128 -> top-100 (8 CTAs) ----------------------
__global__ void k4b_topk(){
    __shared__ unsigned long long sk[1024];
    const int b = blockIdx.x, tid = threadIdx.x;
    for (int i=tid; i<1024; i+=256)
        sk[i] = g_ptop[b*1024 + i];
    __syncthreads();
    for (int k=2; k<=1024; k<<=1){
        for (int j=k>>1; j>0; j>>=1){
            for (int i=tid; i<1024; i+=256){
                int ixj = i^j;
                if (ixj > i){
                    unsigned long long a = sk[i], d = sk[ixj];
                    bool up = (i&k)==0;
                    if (up ? (a<d) : (a>d)){ sk[i]=d; sk[ixj]=a; }
                }
            }
            __syncthreads();
        }
    }
    if (tid < TK){
        unsigned low = (unsigned)sk[tid];
        g_topidx[b*TK + tid] = (int)((0xFFFFFFFFu - low) & 0x3FFFu);
    }
}

// ---------------- K5: gather proposals + pos embeddings --------------------
__global__ void k5_gather(const float* __restrict__ x,
                          const float* __restrict__ pe,
                          float* __restrict__ out){
    const int t = blockIdx.x*256 + threadIdx.x;
    if (t >= BN*CN*TK) return;
    const int k = t % TK;
    const int c = (t / TK) % CN;
    const int b = t / (TK*CN);
    const int idx = g_topidx[b*TK + k];
    out[t]            = x [(size_t)(b*CN + c)*HW + idx];
    out[BN*CN*TK + t] = pe[(size_t)c*HW + idx];
}

// ---------------- launch ----------------------------------------------------
extern "C" void kernel_launch(void* const* d_in, const int* in_sizes, int n_in,
                              void* d_out, int out_size){
    const float* x  = (const float*)d_in[0];
    const float* pe = (const float*)d_in[1];
    const float* w1 = (const float*)d_in[2];
    const float* b1 = (const float*)d_in[3];
    const float* w2 = (const float*)d_in[4];
    const float* b2 = (const float*)d_in[5];
    float* out = (float*)d_out;

    cudaFuncSetAttribute(kmma,   cudaFuncAttributeMaxDynamicSharedMemorySize, 3*STG_SZ);
    cudaFuncSetAttribute(kgemm2, cudaFuncAttributeMaxDynamicSharedMemorySize, 3*STG2_SZ);

    dim3 gt((NPX + 31)/32, BN);
    t_half<<<gt, 256>>>(x);
    k0_wprep<<<(144*16*32*4 + 255)/256, 256>>>(w1, w2);

    dim3 gg(128, 2, BN);
    kmma<<<gg, 256, 3*STG_SZ>>>(b1);

    dim3 g2(128, 1, BN);
    kgemm2<<<g2, 256, 3*STG2_SZ>>>(b2, out);
    k3_boost<<<(BN*HW)/256, 256>>>();
    dim3 g4(8, BN);
    k4a_topk<<<g4, 256>>>();
    k4b_topk<<<BN, 256>>>();
    k5_gather<<<(BN*CN*TK + 255)/256, 256>>>(x, pe, out);
}